// round 11
// baseline (speedup 1.0000x reference)
#include <cuda_runtime.h>
#include <math.h>
#include <stdint.h>

#define BB 16
#define NNX 512
#define CCX 384
#define HHX 6
#define HDX 64
#define FFD 1152
#define BHX (BB*HHX)        // 96
#define MTOK (BB*NNX)       // 8192
#define OUT_ATTN_OFF ((size_t)MTOK*CCX)   // 3145728

// ---------------- device scratch (no dynamic allocation allowed) ----------------
__device__ float g_x[MTOK*CCX];
__device__ float g_q[BHX*NNX*HDX];
__device__ float g_k[BHX*NNX*HDX];
__device__ float g_v[BHX*NNX*HDX];
__device__ float g_qgr[BHX*NNX*HDX];
__device__ float g_kgr[BHX*NNX*HDX];
__device__ float g_qn4[BHX*NNX];
__device__ float g_kn4[BHX*NNX];
__device__ float g_qk[BHX*NNX*NNX];
__device__ float g_dd[BHX*NNX*NNX];
__device__ float g_attnv[MTOK*CCX];
__device__ float g_src1[MTOK*CCX];
__device__ float g_hff[MTOK*FFD];

// ======================= LayerNorm (row of 384, 128 threads) =======================
__global__ void ln_kernel(const float* __restrict__ in, const float* __restrict__ w,
                          const float* __restrict__ b, float* __restrict__ out)
{
    int row = blockIdx.x;
    int t = threadIdx.x;
    const float* p = in + (size_t)row * CCX;
    float v0 = p[t], v1 = p[t + 128], v2 = p[t + 256];
    __shared__ float sh[4];
    float s = v0 + v1 + v2;
#pragma unroll
    for (int o = 16; o; o >>= 1) s += __shfl_xor_sync(0xffffffffu, s, o);
    if ((t & 31) == 0) sh[t >> 5] = s;
    __syncthreads();
    float mu = (sh[0] + sh[1] + sh[2] + sh[3]) * (1.0f / CCX);
    __syncthreads();
    float d0 = v0 - mu, d1 = v1 - mu, d2 = v2 - mu;
    float s2 = d0 * d0 + d1 * d1 + d2 * d2;
#pragma unroll
    for (int o = 16; o; o >>= 1) s2 += __shfl_xor_sync(0xffffffffu, s2, o);
    if ((t & 31) == 0) sh[t >> 5] = s2;
    __syncthreads();
    float var = (sh[0] + sh[1] + sh[2] + sh[3]) * (1.0f / CCX);
    float r = rsqrtf(var + 1e-5f);
    float* q = out + (size_t)row * CCX;
    q[t]       = d0 * r * w[t]       + b[t];
    q[t + 128] = d1 * r * w[t + 128] + b[t + 128];
    q[t + 256] = d2 * r * w[t + 256] + b[t + 256];
}

// ======================= tf32 helpers =======================
__device__ __forceinline__ uint32_t f2tf32(float x) {
    uint32_t r;
    asm("cvt.rna.tf32.f32 %0, %1;" : "=r"(r) : "f"(x));
    return r;
}

__device__ __forceinline__ void mma_tf32(float& d0, float& d1, float& d2, float& d3,
                                         uint32_t a0, uint32_t a1, uint32_t a2, uint32_t a3,
                                         uint32_t b0, uint32_t b1) {
    asm volatile(
        "mma.sync.aligned.m16n8k8.row.col.f32.tf32.tf32.f32 "
        "{%0,%1,%2,%3}, {%4,%5,%6,%7}, {%8,%9}, {%0,%1,%2,%3};\n"
        : "+f"(d0), "+f"(d1), "+f"(d2), "+f"(d3)
        : "r"(a0), "r"(a1), "r"(a2), "r"(a3), "r"(b0), "r"(b1));
}

// ======================= tf32 mma GEMM: C[M,L] = A[M,K] @ W[L,K]^T + bias =======================
#define EPI_NONE 0
#define EPI_QKV  1
#define EPI_GELU 2
#define EPI_RESID 3

template<int EPI>
__global__ __launch_bounds__(256)
void mmgemm_abt(const float* __restrict__ A, const float* __restrict__ W,
                const float* __restrict__ bias, const float* __restrict__ resid,
                float* __restrict__ C, int M, int L, int K)
{
    __shared__ uint32_t As[128 * 20];
    __shared__ uint32_t Ws[128 * 20];
    int m0 = blockIdx.y * 128;
    int l0 = blockIdx.x * 128;
    int t = threadIdx.x;
    int warp = t >> 5, lane = t & 31;
    int g = lane >> 2, tig = lane & 3;
    int wm = warp >> 2, wn = warp & 3;        // warp grid 2 x 4
    int mB = wm * 64, nB = wn * 32;

    float acc[4][4][4];
#pragma unroll
    for (int i = 0; i < 4; i++)
#pragma unroll
        for (int j = 0; j < 4; j++)
#pragma unroll
            for (int v = 0; v < 4; v++) acc[i][j][v] = 0.f;

    int lr = t >> 2;
    int lc = (t & 3) * 4;
    const float* Ap0 = A + (size_t)(m0 + lr) * K + lc;
    const float* Ap1 = A + (size_t)(m0 + 64 + lr) * K + lc;
    const float* Wp0 = W + (size_t)(l0 + lr) * K + lc;
    const float* Wp1 = W + (size_t)(l0 + 64 + lr) * K + lc;

    float4 rA0 = *(const float4*)(Ap0);
    float4 rA1 = *(const float4*)(Ap1);
    float4 rW0 = *(const float4*)(Wp0);
    float4 rW1 = *(const float4*)(Wp1);

    for (int kt = 0; kt < K; kt += 16) {
        {
            uint32_t* as0 = As + lr * 20 + lc;
            uint32_t* as1 = As + (64 + lr) * 20 + lc;
            uint32_t* ws0 = Ws + lr * 20 + lc;
            uint32_t* ws1 = Ws + (64 + lr) * 20 + lc;
            as0[0] = f2tf32(rA0.x); as0[1] = f2tf32(rA0.y); as0[2] = f2tf32(rA0.z); as0[3] = f2tf32(rA0.w);
            as1[0] = f2tf32(rA1.x); as1[1] = f2tf32(rA1.y); as1[2] = f2tf32(rA1.z); as1[3] = f2tf32(rA1.w);
            ws0[0] = f2tf32(rW0.x); ws0[1] = f2tf32(rW0.y); ws0[2] = f2tf32(rW0.z); ws0[3] = f2tf32(rW0.w);
            ws1[0] = f2tf32(rW1.x); ws1[1] = f2tf32(rW1.y); ws1[2] = f2tf32(rW1.z); ws1[3] = f2tf32(rW1.w);
        }
        __syncthreads();
        if (kt + 16 < K) {
            rA0 = *(const float4*)(Ap0 + kt + 16);
            rA1 = *(const float4*)(Ap1 + kt + 16);
            rW0 = *(const float4*)(Wp0 + kt + 16);
            rW1 = *(const float4*)(Wp1 + kt + 16);
        }
#pragma unroll
        for (int ks = 0; ks < 16; ks += 8) {
            uint32_t af[4][4], bf[4][2];
#pragma unroll
            for (int i = 0; i < 4; i++) {
                int base = (mB + i * 16 + g) * 20 + ks + tig;
                af[i][0] = As[base];
                af[i][1] = As[base + 8 * 20];
                af[i][2] = As[base + 4];
                af[i][3] = As[base + 8 * 20 + 4];
            }
#pragma unroll
            for (int j = 0; j < 4; j++) {
                int base = (nB + j * 8 + g) * 20 + ks + tig;
                bf[j][0] = Ws[base];
                bf[j][1] = Ws[base + 4];
            }
#pragma unroll
            for (int i = 0; i < 4; i++)
#pragma unroll
                for (int j = 0; j < 4; j++)
                    mma_tf32(acc[i][j][0], acc[i][j][1], acc[i][j][2], acc[i][j][3],
                             af[i][0], af[i][1], af[i][2], af[i][3],
                             bf[j][0], bf[j][1]);
        }
        __syncthreads();
    }

#pragma unroll
    for (int i = 0; i < 4; i++) {
#pragma unroll
        for (int j = 0; j < 4; j++) {
            int r0 = m0 + mB + i * 16 + g;
            int c0 = l0 + nB + j * 8 + 2 * tig;
            float b0v = bias[c0], b1v = bias[c0 + 1];
#pragma unroll
            for (int half = 0; half < 2; half++) {
                int row = r0 + half * 8;
                float v0 = acc[i][j][half * 2 + 0] + b0v;
                float v1 = acc[i][j][half * 2 + 1] + b1v;
                if (EPI == EPI_NONE) {
                    *(float2*)&C[(size_t)row * L + c0] = make_float2(v0, v1);
                } else if (EPI == EPI_GELU) {
                    v0 = 0.5f * v0 * (1.0f + erff(v0 * 0.70710678118654752f));
                    v1 = 0.5f * v1 * (1.0f + erff(v1 * 0.70710678118654752f));
                    *(float2*)&C[(size_t)row * L + c0] = make_float2(v0, v1);
                } else if (EPI == EPI_RESID) {
                    const float2 rv = *(const float2*)&resid[(size_t)row * L + c0];
                    *(float2*)&C[(size_t)row * L + c0] = make_float2(v0 + rv.x, v1 + rv.y);
                } else { // QKV scatter
#pragma unroll
                    for (int e = 0; e < 2; e++) {
                        int col = c0 + e;
                        float val = (e == 0) ? v0 : v1;
                        int three = col / 384;
                        int rem = col - three * 384;
                        int h = rem >> 6, d = rem & 63;
                        int bb = row >> 9, n = row & 511;
                        float* dst = (three == 0) ? g_q : ((three == 1) ? g_k : g_v);
                        dst[((size_t)(bb * 6 + h) * 512 + n) * 64 + d] = val;
                    }
                }
            }
        }
    }
}

// ======================= batched NT tf32 GEMM: C[bh][512,512] = X[bh] @ Y[bh]^T =======================
// Same fragment structure as mmgemm_abt; Y rows are the B "columns" (row.col NT).
__global__ __launch_bounds__(256)
void bgemm_nt_mma(const float* __restrict__ X, const float* __restrict__ Y, float* __restrict__ C)
{
    __shared__ uint32_t As[128 * 20];
    __shared__ uint32_t Ws[128 * 20];
    int bh = blockIdx.z;
    int m0 = blockIdx.y * 128;
    int n0 = blockIdx.x * 128;
    int t = threadIdx.x;
    int warp = t >> 5, lane = t & 31;
    int g = lane >> 2, tig = lane & 3;
    int wm = warp >> 2, wn = warp & 3;
    int mB = wm * 64, nB = wn * 32;

    const float* Xb = X + (size_t)bh * NNX * HDX;
    const float* Yb = Y + (size_t)bh * NNX * HDX;

    float acc[4][4][4];
#pragma unroll
    for (int i = 0; i < 4; i++)
#pragma unroll
        for (int j = 0; j < 4; j++)
#pragma unroll
            for (int v = 0; v < 4; v++) acc[i][j][v] = 0.f;

    int lr = t >> 2;
    int lc = (t & 3) * 4;
    const float* Ap0 = Xb + (size_t)(m0 + lr) * HDX + lc;
    const float* Ap1 = Xb + (size_t)(m0 + 64 + lr) * HDX + lc;
    const float* Wp0 = Yb + (size_t)(n0 + lr) * HDX + lc;
    const float* Wp1 = Yb + (size_t)(n0 + 64 + lr) * HDX + lc;

    float4 rA0 = *(const float4*)(Ap0);
    float4 rA1 = *(const float4*)(Ap1);
    float4 rW0 = *(const float4*)(Wp0);
    float4 rW1 = *(const float4*)(Wp1);

    for (int kt = 0; kt < HDX; kt += 16) {
        {
            uint32_t* as0 = As + lr * 20 + lc;
            uint32_t* as1 = As + (64 + lr) * 20 + lc;
            uint32_t* ws0 = Ws + lr * 20 + lc;
            uint32_t* ws1 = Ws + (64 + lr) * 20 + lc;
            as0[0] = f2tf32(rA0.x); as0[1] = f2tf32(rA0.y); as0[2] = f2tf32(rA0.z); as0[3] = f2tf32(rA0.w);
            as1[0] = f2tf32(rA1.x); as1[1] = f2tf32(rA1.y); as1[2] = f2tf32(rA1.z); as1[3] = f2tf32(rA1.w);
            ws0[0] = f2tf32(rW0.x); ws0[1] = f2tf32(rW0.y); ws0[2] = f2tf32(rW0.z); ws0[3] = f2tf32(rW0.w);
            ws1[0] = f2tf32(rW1.x); ws1[1] = f2tf32(rW1.y); ws1[2] = f2tf32(rW1.z); ws1[3] = f2tf32(rW1.w);
        }
        __syncthreads();
        if (kt + 16 < HDX) {
            rA0 = *(const float4*)(Ap0 + kt + 16);
            rA1 = *(const float4*)(Ap1 + kt + 16);
            rW0 = *(const float4*)(Wp0 + kt + 16);
            rW1 = *(const float4*)(Wp1 + kt + 16);
        }
#pragma unroll
        for (int ks = 0; ks < 16; ks += 8) {
            uint32_t af[4][4], bf[4][2];
#pragma unroll
            for (int i = 0; i < 4; i++) {
                int base = (mB + i * 16 + g) * 20 + ks + tig;
                af[i][0] = As[base];
                af[i][1] = As[base + 8 * 20];
                af[i][2] = As[base + 4];
                af[i][3] = As[base + 8 * 20 + 4];
            }
#pragma unroll
            for (int j = 0; j < 4; j++) {
                int base = (nB + j * 8 + g) * 20 + ks + tig;
                bf[j][0] = Ws[base];
                bf[j][1] = Ws[base + 4];
            }
#pragma unroll
            for (int i = 0; i < 4; i++)
#pragma unroll
                for (int j = 0; j < 4; j++)
                    mma_tf32(acc[i][j][0], acc[i][j][1], acc[i][j][2], acc[i][j][3],
                             af[i][0], af[i][1], af[i][2], af[i][3],
                             bf[j][0], bf[j][1]);
        }
        __syncthreads();
    }

    float* Cp = C + (size_t)bh * NNX * NNX;
#pragma unroll
    for (int i = 0; i < 4; i++) {
#pragma unroll
        for (int j = 0; j < 4; j++) {
            int r0 = m0 + mB + i * 16 + g;
            int c0 = n0 + nB + j * 8 + 2 * tig;
#pragma unroll
            for (int half = 0; half < 2; half++) {
                int row = r0 + half * 8;
                *(float2*)&Cp[(size_t)row * NNX + c0] =
                    make_float2(acc[i][j][half * 2 + 0], acc[i][j][half * 2 + 1]);
            }
        }
    }
}

// ======================= per-row squared-norms^2 =======================
__global__ void norms_kernel()
{
    int idx = blockIdx.x * 256 + threadIdx.x;
    if (idx >= BHX * NNX) return;
    const float* pq = g_q + (size_t)idx * 64;
    const float* pk = g_k + (size_t)idx * 64;
    float sq = 0.f, sk = 0.f;
#pragma unroll
    for (int d = 0; d < 64; d++) { sq += pq[d] * pq[d]; sk += pk[d] * pk[d]; }
    g_qn4[idx] = sq * sq;
    g_kn4[idx] = sk * sk;
}

// ======================= register-resident Householder QR (512x64, reduced Q) =======================
__global__ __launch_bounds__(512, 1)
void qr_kernel2(const float* __restrict__ X0, float* __restrict__ Q0,
                const float* __restrict__ X1, float* __restrict__ Q1)
{
    int bh = blockIdx.x;
    const float* src = (bh < BHX) ? (X0 + (size_t)bh * 512 * 64)
                                  : (X1 + (size_t)(bh - BHX) * 512 * 64);
    float* dst = (bh < BHX) ? (Q0 + (size_t)bh * 512 * 64)
                            : (Q1 + (size_t)(bh - BHX) * 512 * 64);
    int t = threadIdx.x;
    int w = t >> 5, l = t & 31;
    __shared__ float vsh[2][512];
    __shared__ float tauv[64];

    float a[4][16];
#pragma unroll
    for (int r = 0; r < 16; r++) {
        float4 v4 = *(const float4*)(src + (size_t)(16 * l + r) * 64 + 4 * w);
        a[0][r] = v4.x; a[1][r] = v4.y; a[2][r] = v4.z; a[3][r] = v4.w;
    }

    for (int j = 0; j < 64; j++) {
        int jw = j >> 2, jc = j & 3;
        float* vb = vsh[j & 1];
        if (w == jw) {
#pragma unroll
            for (int cc = 0; cc < 4; cc++) if (cc == jc) {
                float n2 = 0.f, al = 0.f;
#pragma unroll
                for (int r = 0; r < 16; r++) {
                    int i = 16 * l + r;
                    float x = a[cc][r];
                    n2 += (i > j) ? x * x : 0.f;
                    al += (i == j) ? x : 0.f;
                }
#pragma unroll
                for (int o = 16; o; o >>= 1) {
                    n2 += __shfl_xor_sync(0xffffffffu, n2, o);
                    al += __shfl_xor_sync(0xffffffffu, al, o);
                }
                float tau, scal;
                if (n2 == 0.f) { tau = 0.f; scal = 0.f; }
                else {
                    float beta = -copysignf(sqrtf(al * al + n2), al);
                    tau  = (beta - al) / beta;
                    scal = 1.0f / (al - beta);
                }
#pragma unroll
                for (int r = 0; r < 16; r++) {
                    int i = 16 * l + r;
                    float vv;
                    if (i < j) vv = 0.f;
                    else if (i == j) vv = 1.f;
                    else { vv = a[cc][r] * scal; a[cc][r] = vv; }
                    vb[i] = vv;
                }
                if (l == 0) tauv[j] = tau;
            }
        }
        __syncthreads();
        float tau = tauv[j];
        if (tau != 0.f && (4 * w + 3) > j) {
            float vr[16];
#pragma unroll
            for (int r = 0; r < 16; r++) vr[r] = vb[16 * l + r];
#pragma unroll
            for (int c = 0; c < 4; c++) {
                int C = 4 * w + c;
                if (C > j) {
                    float s = 0.f;
#pragma unroll
                    for (int r = 0; r < 16; r++) s += vr[r] * a[c][r];
#pragma unroll
                    for (int o = 16; o; o >>= 1) s += __shfl_xor_sync(0xffffffffu, s, o);
                    float wc = tau * s;
#pragma unroll
                    for (int r = 0; r < 16; r++) a[c][r] -= vr[r] * wc;
                }
            }
        }
    }
    __syncthreads();

    for (int j = 63; j >= 0; j--) {
        int jw = j >> 2, jc = j & 3;
        float tau = tauv[j];
        float* vb = vsh[j & 1];
        if (w == jw) {
#pragma unroll
            for (int cc = 0; cc < 4; cc++) if (cc == jc) {
#pragma unroll
                for (int r = 0; r < 16; r++) {
                    int i = 16 * l + r;
                    float vv;
                    if (i < j) vv = 0.f;
                    else if (i == j) vv = 1.f;
                    else vv = a[cc][r];
                    vb[i] = vv;
                }
            }
        }
        __syncthreads();
        if (tau != 0.f && (4 * w + 3) > j) {
            float vr[16];
#pragma unroll
            for (int r = 0; r < 16; r++) vr[r] = vb[16 * l + r];
#pragma unroll
            for (int c = 0; c < 4; c++) {
                int C = 4 * w + c;
                if (C > j) {
                    float s = 0.f;
#pragma unroll
                    for (int r = 0; r < 16; r++) s += vr[r] * a[c][r];
#pragma unroll
                    for (int o = 16; o; o >>= 1) s += __shfl_xor_sync(0xffffffffu, s, o);
                    float wc = tau * s;
#pragma unroll
                    for (int r = 0; r < 16; r++) a[c][r] -= vr[r] * wc;
                }
            }
        }
        if (w == jw) {
#pragma unroll
            for (int cc = 0; cc < 4; cc++) if (cc == jc) {
#pragma unroll
                for (int r = 0; r < 16; r++) {
                    int i = 16 * l + r;
                    float val;
                    if (i < j) val = 0.f;
                    else if (i == j) val = 1.f - tau;
                    else val = -tau * a[cc][r];
                    a[cc][r] = val;
                }
            }
        }
    }
    __syncthreads();

#pragma unroll
    for (int r = 0; r < 16; r++) {
        float4 v4 = make_float4(a[0][r], a[1][r], a[2][r], a[3][r]);
        *(float4*)(dst + (size_t)(16 * l + r) * 64 + 4 * w) = v4;
    }
}

// ======================= fused 18->6 channel mix + softmax =======================
__global__ __launch_bounds__(512)
void mix_softmax(const float* __restrict__ scale_p, const float* __restrict__ rs_p,
                 const float* __restrict__ gs_p, const float* __restrict__ conv_w,
                 const float* __restrict__ conv_b, float* __restrict__ attn_out)
{
    int bn = blockIdx.x;
    int b = bn >> 9, n = bn & 511;
    int t = threadIdx.x;
    __shared__ float cw[108], cb[6], sq4[6], sca[3];
    __shared__ float red2[16];
    if (t < 108) cw[t] = conv_w[t];
    if (t < 6) { cb[t] = conv_b[t]; sq4[t] = g_qn4[(b * 6 + t) * 512 + n]; }
    if (t == 120) sca[0] = scale_p[0];
    if (t == 121) sca[1] = rs_p[0];
    if (t == 122) sca[2] = gs_p[0];
    __syncthreads();

    float mix[6];
#pragma unroll
    for (int o = 0; o < 6; o++) mix[o] = cb[o];
#pragma unroll
    for (int h = 0; h < 6; h++) {
        size_t base = ((size_t)(b * 6 + h) * 512 + n) * 512 + t;
        float qk = g_qk[base];
        float dd = g_dd[base];
        float kn4 = g_kn4[(b * 6 + h) * 512 + t];
        float eu = qk * sca[0];
        float ri = sqrtf(fmaxf(sq4[h] + kn4 - 2.0f * qk * qk, 0.0f)) * sca[1];
        float gr = dd * dd * sca[2];
#pragma unroll
        for (int o = 0; o < 6; o++)
            mix[o] += cw[o * 18 + h] * eu + cw[o * 18 + 6 + h] * ri + cw[o * 18 + 12 + h] * gr;
    }

    int lane = t & 31, wid = t >> 5;
    for (int o = 0; o < 6; o++) {
        float v = mix[o];
#pragma unroll
        for (int of = 16; of; of >>= 1) v = fmaxf(v, __shfl_xor_sync(0xffffffffu, v, of));
        if (lane == 0) red2[wid] = v;
        __syncthreads();
        if (t < 32) {
            float x = (t < 16) ? red2[t] : -3.4e38f;
#pragma unroll
            for (int of = 8; of; of >>= 1) x = fmaxf(x, __shfl_xor_sync(0xffffffffu, x, of));
            if (t == 0) red2[0] = x;
        }
        __syncthreads();
        float mx = red2[0];
        __syncthreads();
        float e = expf(mix[o] - mx);
        float s = e;
#pragma unroll
        for (int of = 16; of; of >>= 1) s += __shfl_xor_sync(0xffffffffu, s, of);
        if (lane == 0) red2[wid] = s;
        __syncthreads();
        if (t < 32) {
            float x = (t < 16) ? red2[t] : 0.f;
#pragma unroll
            for (int of = 8; of; of >>= 1) x += __shfl_xor_sync(0xffffffffu, x, of);
            if (t == 0) red2[0] = x;
        }
        __syncthreads();
        float r = e / red2[0];
        attn_out[((size_t)(b * 6 + o) * 512 + n) * 512 + t] = r;
        __syncthreads();
    }
}

// ======================= batched attn @ V (tf32 mma), scattered to [B,N,C] =======================
// CTA tile 128x64 (M x N), warp grid 2x4 -> warp tile 64x16. K = 512, k-tile 16.
__global__ __launch_bounds__(256)
void bgemm_av_mma(const float* __restrict__ attn)
{
    __shared__ uint32_t As[128 * 20];
    __shared__ uint32_t Vs[64 * 20];
    int bh = blockIdx.y;
    int m0 = blockIdx.x * 128;
    int b = bh / 6, h = bh - b * 6;
    int t = threadIdx.x;
    int warp = t >> 5, lane = t & 31;
    int g = lane >> 2, tig = lane & 3;
    int wm = warp >> 2, wn = warp & 3;
    int mB = wm * 64, nB = wn * 16;

    const float* Ap = attn + (size_t)bh * NNX * NNX;
    const float* Vp = g_v + (size_t)bh * NNX * HDX;

    float acc[4][2][4];
#pragma unroll
    for (int i = 0; i < 4; i++)
#pragma unroll
        for (int j = 0; j < 2; j++)
#pragma unroll
            for (int v = 0; v < 4; v++) acc[i][j][v] = 0.f;

    int lr = t >> 2;
    int lc = (t & 3) * 4;
    const float* Ap0 = Ap + (size_t)(m0 + lr) * NNX + lc;
    const float* Ap1 = Ap + (size_t)(m0 + 64 + lr) * NNX + lc;
    // V transpose-load coords: element e -> k = e>>6 (0..15), n = e&63
    int vk0 = t >> 6, vn = t & 63;           // u adds 4 to vk

    float4 rA0 = *(const float4*)(Ap0);
    float4 rA1 = *(const float4*)(Ap1);
    float rV[4];
#pragma unroll
    for (int u = 0; u < 4; u++)
        rV[u] = Vp[(size_t)(vk0 + u * 4) * HDX + vn];

    for (int kt = 0; kt < NNX; kt += 16) {
        {
            uint32_t* as0 = As + lr * 20 + lc;
            uint32_t* as1 = As + (64 + lr) * 20 + lc;
            as0[0] = f2tf32(rA0.x); as0[1] = f2tf32(rA0.y); as0[2] = f2tf32(rA0.z); as0[3] = f2tf32(rA0.w);
            as1[0] = f2tf32(rA1.x); as1[1] = f2tf32(rA1.y); as1[2] = f2tf32(rA1.z); as1[3] = f2tf32(rA1.w);
#pragma unroll
            for (int u = 0; u < 4; u++)
                Vs[vn * 20 + vk0 + u * 4] = f2tf32(rV[u]);
        }
        __syncthreads();
        if (kt + 16 < NNX) {
            rA0 = *(const float4*)(Ap0 + kt + 16);
            rA1 = *(const float4*)(Ap1 + kt + 16);
#pragma unroll
            for (int u = 0; u < 4; u++)
                rV[u] = Vp[(size_t)(kt + 16 + vk0 + u * 4) * HDX + vn];
        }
#pragma unroll
        for (int ks = 0; ks < 16; ks += 8) {
            uint32_t af[4][4], bf[2][2];
#pragma unroll
            for (int i = 0; i < 4; i++) {
                int base = (mB + i * 16 + g) * 20 + ks + tig;
                af[i][0] = As[base];
                af[i][1] = As[base + 8 * 20];
                af[i][2] = As[base + 4];
                af[i][3] = As[base + 8 * 20 + 4];
            }
#pragma unroll
            for (int j = 0; j < 2; j++) {
                int base = (nB + j * 8 + g) * 20 + ks + tig;
                bf[j][0] = Vs[base];
                bf[j][1] = Vs[base + 4];
            }
#pragma unroll
            for (int i = 0; i < 4; i++)
#pragma unroll
                for (int j = 0; j < 2; j++)
                    mma_tf32(acc[i][j][0], acc[i][j][1], acc[i][j][2], acc[i][j][3],
                             af[i][0], af[i][1], af[i][2], af[i][3],
                             bf[j][0], bf[j][1]);
        }
        __syncthreads();
    }

#pragma unroll
    for (int i = 0; i < 4; i++) {
#pragma unroll
        for (int j = 0; j < 2; j++) {
            int r0 = m0 + mB + i * 16 + g;
            int c0 = nB + j * 8 + 2 * tig;
#pragma unroll
            for (int half = 0; half < 2; half++) {
                int m = r0 + half * 8;
                *(float2*)&g_attnv[(size_t)(b * 512 + m) * CCX + h * 64 + c0] =
                    make_float2(acc[i][j][half * 2 + 0], acc[i][j][half * 2 + 1]);
            }
        }
    }
}

// ======================= launch =======================
extern "C" void kernel_launch(void* const* d_in, const int* in_sizes, int n_in,
                              void* d_out, int out_size)
{
    const float* src    = (const float*)d_in[0];
    const float* pre_w  = (const float*)d_in[1];
    const float* pre_b  = (const float*)d_in[2];
    const float* qkv_w  = (const float*)d_in[3];
    const float* qkv_b  = (const float*)d_in[4];
    const float* scale  = (const float*)d_in[5];
    const float* riem   = (const float*)d_in[6];
    const float* grass  = (const float*)d_in[7];
    const float* conv_w = (const float*)d_in[8];
    const float* conv_b = (const float*)d_in[9];
    const float* proj_w = (const float*)d_in[10];
    const float* proj_b = (const float*)d_in[11];
    const float* n1_w   = (const float*)d_in[12];
    const float* n1_b   = (const float*)d_in[13];
    const float* l1_w   = (const float*)d_in[14];
    const float* l1_b   = (const float*)d_in[15];
    const float* l2_w   = (const float*)d_in[16];
    const float* l2_b   = (const float*)d_in[17];
    float* out = (float*)d_out;

    void *p_x, *p_q, *p_k, *p_qgr, *p_kgr, *p_qk, *p_dd, *p_attnv, *p_src1, *p_hff;
    cudaGetSymbolAddress(&p_x, g_x);
    cudaGetSymbolAddress(&p_q, g_q);
    cudaGetSymbolAddress(&p_k, g_k);
    cudaGetSymbolAddress(&p_qgr, g_qgr);
    cudaGetSymbolAddress(&p_kgr, g_kgr);
    cudaGetSymbolAddress(&p_qk, g_qk);
    cudaGetSymbolAddress(&p_dd, g_dd);
    cudaGetSymbolAddress(&p_attnv, g_attnv);
    cudaGetSymbolAddress(&p_src1, g_src1);
    cudaGetSymbolAddress(&p_hff, g_hff);

    // 1. pre-LN
    ln_kernel<<<MTOK, 128>>>(src, pre_w, pre_b, (float*)p_x);
    // 2. QKV projection (tf32 mma), scattered into per-head q/k/v
    mmgemm_abt<EPI_QKV><<<dim3(FFD / 128, MTOK / 128), 256>>>(
        (const float*)p_x, qkv_w, qkv_b, nullptr, nullptr, MTOK, FFD, CCX);
    // 3. row norms^4
    norms_kernel<<<(BHX * NNX + 255) / 256, 256>>>();
    // 4. register-resident Householder QR, q and k in one launch (192 blocks)
    qr_kernel2<<<2 * BHX, 512>>>((const float*)p_q, (float*)p_qgr,
                                 (const float*)p_k, (float*)p_kgr);
    // 5. score GEMMs (tf32 mma)
    bgemm_nt_mma<<<dim3(4, 4, BHX), 256>>>((const float*)p_q, (const float*)p_k, (float*)p_qk);
    bgemm_nt_mma<<<dim3(4, 4, BHX), 256>>>((const float*)p_qgr, (const float*)p_kgr, (float*)p_dd);
    // 6. fused channel-mix + softmax -> attn output region of d_out
    float* attn_out = out + OUT_ATTN_OFF;
    mix_softmax<<<MTOK, 512>>>(scale, riem, grass, conv_w, conv_b, attn_out);
    // 7. attn @ V (tf32 mma) -> [B,N,C] layout
    bgemm_av_mma<<<dim3(4, BHX), 256>>>(attn_out);
    // 8. output projection + residual with original src (tf32 mma)
    mmgemm_abt<EPI_RESID><<<dim3(CCX / 128, MTOK / 128), 256>>>(
        (const float*)p_attnv, proj_w, proj_b, src, (float*)p_src1, MTOK, CCX, CCX);
    // 9. norm1
    ln_kernel<<<MTOK, 128>>>((const float*)p_src1, n1_w, n1_b, (float*)p_x);
    // 10. FF lin1 + exact GELU (tf32 mma)
    mmgemm_abt<EPI_GELU><<<dim3(FFD / 128, MTOK / 128), 256>>>(
        (const float*)p_x, l1_w, l1_b, nullptr, (float*)p_hff, MTOK, FFD, CCX);
    // 11. FF lin2 + residual -> src part of d_out (tf32 mma)
    mmgemm_abt<EPI_RESID><<<dim3(CCX / 128, MTOK / 128), 256>>>(
        (const float*)p_hff, l2_w, l2_b, (const float*)p_x, out, MTOK, CCX, FFD);

    (void)in_sizes; (void)n_in; (void)out_size;
}

// round 12
// speedup vs baseline: 1.5590x; 1.5590x over previous
#include <cuda_runtime.h>
#include <math.h>
#include <stdint.h>

#define BB 16
#define NNX 512
#define CCX 384
#define HHX 6
#define HDX 64
#define FFD 1152
#define BHX (BB*HHX)        // 96
#define MTOK (BB*NNX)       // 8192
#define OUT_ATTN_OFF ((size_t)MTOK*CCX)   // 3145728

// ---------------- device scratch (no dynamic allocation allowed) ----------------
__device__ float g_x[MTOK*CCX];
__device__ float g_q[BHX*NNX*HDX];
__device__ float g_k[BHX*NNX*HDX];
__device__ float g_v[BHX*NNX*HDX];
__device__ float g_qgr[BHX*NNX*HDX];
__device__ float g_kgr[BHX*NNX*HDX];
__device__ float g_qn4[BHX*NNX];
__device__ float g_kn4[BHX*NNX];
__device__ float g_qk[BHX*NNX*NNX];
__device__ float g_dd[BHX*NNX*NNX];
__device__ float g_attnv[MTOK*CCX];
__device__ float g_src1[MTOK*CCX];
__device__ float g_hff[MTOK*FFD];

// ======================= LayerNorm (row of 384, 128 threads) =======================
__global__ void ln_kernel(const float* __restrict__ in, const float* __restrict__ w,
                          const float* __restrict__ b, float* __restrict__ out)
{
    int row = blockIdx.x;
    int t = threadIdx.x;
    const float* p = in + (size_t)row * CCX;
    float v0 = p[t], v1 = p[t + 128], v2 = p[t + 256];
    __shared__ float sh[4];
    float s = v0 + v1 + v2;
#pragma unroll
    for (int o = 16; o; o >>= 1) s += __shfl_xor_sync(0xffffffffu, s, o);
    if ((t & 31) == 0) sh[t >> 5] = s;
    __syncthreads();
    float mu = (sh[0] + sh[1] + sh[2] + sh[3]) * (1.0f / CCX);
    __syncthreads();
    float d0 = v0 - mu, d1 = v1 - mu, d2 = v2 - mu;
    float s2 = d0 * d0 + d1 * d1 + d2 * d2;
#pragma unroll
    for (int o = 16; o; o >>= 1) s2 += __shfl_xor_sync(0xffffffffu, s2, o);
    if ((t & 31) == 0) sh[t >> 5] = s2;
    __syncthreads();
    float var = (sh[0] + sh[1] + sh[2] + sh[3]) * (1.0f / CCX);
    float r = rsqrtf(var + 1e-5f);
    float* q = out + (size_t)row * CCX;
    q[t]       = d0 * r * w[t]       + b[t];
    q[t + 128] = d1 * r * w[t + 128] + b[t + 128];
    q[t + 256] = d2 * r * w[t + 256] + b[t + 256];
}

// ======================= tf32 helpers =======================
__device__ __forceinline__ uint32_t f2tf32(float x) {
    uint32_t r;
    asm("cvt.rna.tf32.f32 %0, %1;" : "=r"(r) : "f"(x));
    return r;
}

__device__ __forceinline__ void mma_tf32(float& d0, float& d1, float& d2, float& d3,
                                         uint32_t a0, uint32_t a1, uint32_t a2, uint32_t a3,
                                         uint32_t b0, uint32_t b1) {
    asm volatile(
        "mma.sync.aligned.m16n8k8.row.col.f32.tf32.tf32.f32 "
        "{%0,%1,%2,%3}, {%4,%5,%6,%7}, {%8,%9}, {%0,%1,%2,%3};\n"
        : "+f"(d0), "+f"(d1), "+f"(d2), "+f"(d3)
        : "r"(a0), "r"(a1), "r"(a2), "r"(a3), "r"(b0), "r"(b1));
}

// ======================= tf32 mma GEMM: C[M,L] = A[M,K] @ W[L,K]^T + bias =======================
#define EPI_NONE 0
#define EPI_QKV  1
#define EPI_GELU 2
#define EPI_RESID 3

template<int EPI>
__global__ __launch_bounds__(256)
void mmgemm_abt(const float* __restrict__ A, const float* __restrict__ W,
                const float* __restrict__ bias, const float* __restrict__ resid,
                float* __restrict__ C, int M, int L, int K)
{
    __shared__ uint32_t As[128 * 20];
    __shared__ uint32_t Ws[128 * 20];
    int m0 = blockIdx.y * 128;
    int l0 = blockIdx.x * 128;
    int t = threadIdx.x;
    int warp = t >> 5, lane = t & 31;
    int g = lane >> 2, tig = lane & 3;
    int wm = warp >> 2, wn = warp & 3;        // warp grid 2 x 4
    int mB = wm * 64, nB = wn * 32;

    float acc[4][4][4];
#pragma unroll
    for (int i = 0; i < 4; i++)
#pragma unroll
        for (int j = 0; j < 4; j++)
#pragma unroll
            for (int v = 0; v < 4; v++) acc[i][j][v] = 0.f;

    int lr = t >> 2;
    int lc = (t & 3) * 4;
    const float* Ap0 = A + (size_t)(m0 + lr) * K + lc;
    const float* Ap1 = A + (size_t)(m0 + 64 + lr) * K + lc;
    const float* Wp0 = W + (size_t)(l0 + lr) * K + lc;
    const float* Wp1 = W + (size_t)(l0 + 64 + lr) * K + lc;

    float4 rA0 = *(const float4*)(Ap0);
    float4 rA1 = *(const float4*)(Ap1);
    float4 rW0 = *(const float4*)(Wp0);
    float4 rW1 = *(const float4*)(Wp1);

    for (int kt = 0; kt < K; kt += 16) {
        {
            uint32_t* as0 = As + lr * 20 + lc;
            uint32_t* as1 = As + (64 + lr) * 20 + lc;
            uint32_t* ws0 = Ws + lr * 20 + lc;
            uint32_t* ws1 = Ws + (64 + lr) * 20 + lc;
            as0[0] = f2tf32(rA0.x); as0[1] = f2tf32(rA0.y); as0[2] = f2tf32(rA0.z); as0[3] = f2tf32(rA0.w);
            as1[0] = f2tf32(rA1.x); as1[1] = f2tf32(rA1.y); as1[2] = f2tf32(rA1.z); as1[3] = f2tf32(rA1.w);
            ws0[0] = f2tf32(rW0.x); ws0[1] = f2tf32(rW0.y); ws0[2] = f2tf32(rW0.z); ws0[3] = f2tf32(rW0.w);
            ws1[0] = f2tf32(rW1.x); ws1[1] = f2tf32(rW1.y); ws1[2] = f2tf32(rW1.z); ws1[3] = f2tf32(rW1.w);
        }
        __syncthreads();
        if (kt + 16 < K) {
            rA0 = *(const float4*)(Ap0 + kt + 16);
            rA1 = *(const float4*)(Ap1 + kt + 16);
            rW0 = *(const float4*)(Wp0 + kt + 16);
            rW1 = *(const float4*)(Wp1 + kt + 16);
        }
#pragma unroll
        for (int ks = 0; ks < 16; ks += 8) {
            uint32_t af[4][4], bf[4][2];
#pragma unroll
            for (int i = 0; i < 4; i++) {
                int base = (mB + i * 16 + g) * 20 + ks + tig;
                af[i][0] = As[base];
                af[i][1] = As[base + 8 * 20];
                af[i][2] = As[base + 4];
                af[i][3] = As[base + 8 * 20 + 4];
            }
#pragma unroll
            for (int j = 0; j < 4; j++) {
                int base = (nB + j * 8 + g) * 20 + ks + tig;
                bf[j][0] = Ws[base];
                bf[j][1] = Ws[base + 4];
            }
#pragma unroll
            for (int i = 0; i < 4; i++)
#pragma unroll
                for (int j = 0; j < 4; j++)
                    mma_tf32(acc[i][j][0], acc[i][j][1], acc[i][j][2], acc[i][j][3],
                             af[i][0], af[i][1], af[i][2], af[i][3],
                             bf[j][0], bf[j][1]);
        }
        __syncthreads();
    }

#pragma unroll
    for (int i = 0; i < 4; i++) {
#pragma unroll
        for (int j = 0; j < 4; j++) {
            int r0 = m0 + mB + i * 16 + g;
            int c0 = l0 + nB + j * 8 + 2 * tig;
            float b0v = bias[c0], b1v = bias[c0 + 1];
#pragma unroll
            for (int half = 0; half < 2; half++) {
                int row = r0 + half * 8;
                float v0 = acc[i][j][half * 2 + 0] + b0v;
                float v1 = acc[i][j][half * 2 + 1] + b1v;
                if (EPI == EPI_NONE) {
                    *(float2*)&C[(size_t)row * L + c0] = make_float2(v0, v1);
                } else if (EPI == EPI_GELU) {
                    v0 = 0.5f * v0 * (1.0f + erff(v0 * 0.70710678118654752f));
                    v1 = 0.5f * v1 * (1.0f + erff(v1 * 0.70710678118654752f));
                    *(float2*)&C[(size_t)row * L + c0] = make_float2(v0, v1);
                } else if (EPI == EPI_RESID) {
                    const float2 rv = *(const float2*)&resid[(size_t)row * L + c0];
                    *(float2*)&C[(size_t)row * L + c0] = make_float2(v0 + rv.x, v1 + rv.y);
                } else { // QKV scatter
#pragma unroll
                    for (int e = 0; e < 2; e++) {
                        int col = c0 + e;
                        float val = (e == 0) ? v0 : v1;
                        int three = col / 384;
                        int rem = col - three * 384;
                        int h = rem >> 6, d = rem & 63;
                        int bb = row >> 9, n = row & 511;
                        float* dst = (three == 0) ? g_q : ((three == 1) ? g_k : g_v);
                        dst[((size_t)(bb * 6 + h) * 512 + n) * 64 + d] = val;
                    }
                }
            }
        }
    }
}

// ======================= batched NT tf32 GEMM (both score GEMMs in ONE launch) =======================
// grid.z in [0, 2*BHX): z < BHX -> qk = q @ k^T for head z; else dd = qgr @ kgr^T for head z-BHX.
// __launch_bounds__(256,2): cap 128 regs -> 2 CTAs/SM for latency hiding (K=64 is prologue-bound).
__global__ __launch_bounds__(256, 2)
void bgemm_nt_mma(const float* __restrict__ Q, const float* __restrict__ Km,
                  const float* __restrict__ Qg, const float* __restrict__ Kg,
                  float* __restrict__ Cqk, float* __restrict__ Cdd)
{
    __shared__ uint32_t As[128 * 20];
    __shared__ uint32_t Ws[128 * 20];
    int z = blockIdx.z;
    int bh = (z < BHX) ? z : (z - BHX);
    const float* X = (z < BHX) ? Q : Qg;
    const float* Y = (z < BHX) ? Km : Kg;
    float* C = (z < BHX) ? Cqk : Cdd;
    int m0 = blockIdx.y * 128;
    int n0 = blockIdx.x * 128;
    int t = threadIdx.x;
    int warp = t >> 5, lane = t & 31;
    int g = lane >> 2, tig = lane & 3;
    int wm = warp >> 2, wn = warp & 3;
    int mB = wm * 64, nB = wn * 32;

    const float* Xb = X + (size_t)bh * NNX * HDX;
    const float* Yb = Y + (size_t)bh * NNX * HDX;

    float acc[4][4][4];
#pragma unroll
    for (int i = 0; i < 4; i++)
#pragma unroll
        for (int j = 0; j < 4; j++)
#pragma unroll
            for (int v = 0; v < 4; v++) acc[i][j][v] = 0.f;

    int lr = t >> 2;
    int lc = (t & 3) * 4;
    const float* Ap0 = Xb + (size_t)(m0 + lr) * HDX + lc;
    const float* Ap1 = Xb + (size_t)(m0 + 64 + lr) * HDX + lc;
    const float* Wp0 = Yb + (size_t)(n0 + lr) * HDX + lc;
    const float* Wp1 = Yb + (size_t)(n0 + 64 + lr) * HDX + lc;

    float4 rA0 = *(const float4*)(Ap0);
    float4 rA1 = *(const float4*)(Ap1);
    float4 rW0 = *(const float4*)(Wp0);
    float4 rW1 = *(const float4*)(Wp1);

    for (int kt = 0; kt < HDX; kt += 16) {
        {
            uint32_t* as0 = As + lr * 20 + lc;
            uint32_t* as1 = As + (64 + lr) * 20 + lc;
            uint32_t* ws0 = Ws + lr * 20 + lc;
            uint32_t* ws1 = Ws + (64 + lr) * 20 + lc;
            as0[0] = f2tf32(rA0.x); as0[1] = f2tf32(rA0.y); as0[2] = f2tf32(rA0.z); as0[3] = f2tf32(rA0.w);
            as1[0] = f2tf32(rA1.x); as1[1] = f2tf32(rA1.y); as1[2] = f2tf32(rA1.z); as1[3] = f2tf32(rA1.w);
            ws0[0] = f2tf32(rW0.x); ws0[1] = f2tf32(rW0.y); ws0[2] = f2tf32(rW0.z); ws0[3] = f2tf32(rW0.w);
            ws1[0] = f2tf32(rW1.x); ws1[1] = f2tf32(rW1.y); ws1[2] = f2tf32(rW1.z); ws1[3] = f2tf32(rW1.w);
        }
        __syncthreads();
        if (kt + 16 < HDX) {
            rA0 = *(const float4*)(Ap0 + kt + 16);
            rA1 = *(const float4*)(Ap1 + kt + 16);
            rW0 = *(const float4*)(Wp0 + kt + 16);
            rW1 = *(const float4*)(Wp1 + kt + 16);
        }
#pragma unroll
        for (int ks = 0; ks < 16; ks += 8) {
            uint32_t af[4][4], bf[4][2];
#pragma unroll
            for (int i = 0; i < 4; i++) {
                int base = (mB + i * 16 + g) * 20 + ks + tig;
                af[i][0] = As[base];
                af[i][1] = As[base + 8 * 20];
                af[i][2] = As[base + 4];
                af[i][3] = As[base + 8 * 20 + 4];
            }
#pragma unroll
            for (int j = 0; j < 4; j++) {
                int base = (nB + j * 8 + g) * 20 + ks + tig;
                bf[j][0] = Ws[base];
                bf[j][1] = Ws[base + 4];
            }
#pragma unroll
            for (int i = 0; i < 4; i++)
#pragma unroll
                for (int j = 0; j < 4; j++)
                    mma_tf32(acc[i][j][0], acc[i][j][1], acc[i][j][2], acc[i][j][3],
                             af[i][0], af[i][1], af[i][2], af[i][3],
                             bf[j][0], bf[j][1]);
        }
        __syncthreads();
    }

    float* Cp = C + (size_t)bh * NNX * NNX;
#pragma unroll
    for (int i = 0; i < 4; i++) {
#pragma unroll
        for (int j = 0; j < 4; j++) {
            int r0 = m0 + mB + i * 16 + g;
            int c0 = n0 + nB + j * 8 + 2 * tig;
#pragma unroll
            for (int half = 0; half < 2; half++) {
                int row = r0 + half * 8;
                *(float2*)&Cp[(size_t)row * NNX + c0] =
                    make_float2(acc[i][j][half * 2 + 0], acc[i][j][half * 2 + 1]);
            }
        }
    }
}

// ======================= per-row squared-norms^2 =======================
__global__ void norms_kernel()
{
    int idx = blockIdx.x * 256 + threadIdx.x;
    if (idx >= BHX * NNX) return;
    const float* pq = g_q + (size_t)idx * 64;
    const float* pk = g_k + (size_t)idx * 64;
    float sq = 0.f, sk = 0.f;
#pragma unroll
    for (int d = 0; d < 64; d++) { sq += pq[d] * pq[d]; sk += pk[d] * pk[d]; }
    g_qn4[idx] = sq * sq;
    g_kn4[idx] = sk * sk;
}

// ======================= register-resident Householder QR (512x64, reduced Q) =======================
__global__ __launch_bounds__(512, 1)
void qr_kernel2(const float* __restrict__ X0, float* __restrict__ Q0,
                const float* __restrict__ X1, float* __restrict__ Q1)
{
    int bh = blockIdx.x;
    const float* src = (bh < BHX) ? (X0 + (size_t)bh * 512 * 64)
                                  : (X1 + (size_t)(bh - BHX) * 512 * 64);
    float* dst = (bh < BHX) ? (Q0 + (size_t)bh * 512 * 64)
                            : (Q1 + (size_t)(bh - BHX) * 512 * 64);
    int t = threadIdx.x;
    int w = t >> 5, l = t & 31;
    __shared__ float vsh[2][512];
    __shared__ float tauv[64];

    float a[4][16];
#pragma unroll
    for (int r = 0; r < 16; r++) {
        float4 v4 = *(const float4*)(src + (size_t)(16 * l + r) * 64 + 4 * w);
        a[0][r] = v4.x; a[1][r] = v4.y; a[2][r] = v4.z; a[3][r] = v4.w;
    }

    for (int j = 0; j < 64; j++) {
        int jw = j >> 2, jc = j & 3;
        float* vb = vsh[j & 1];
        if (w == jw) {
#pragma unroll
            for (int cc = 0; cc < 4; cc++) if (cc == jc) {
                float n2 = 0.f, al = 0.f;
#pragma unroll
                for (int r = 0; r < 16; r++) {
                    int i = 16 * l + r;
                    float x = a[cc][r];
                    n2 += (i > j) ? x * x : 0.f;
                    al += (i == j) ? x : 0.f;
                }
#pragma unroll
                for (int o = 16; o; o >>= 1) {
                    n2 += __shfl_xor_sync(0xffffffffu, n2, o);
                    al += __shfl_xor_sync(0xffffffffu, al, o);
                }
                float tau, scal;
                if (n2 == 0.f) { tau = 0.f; scal = 0.f; }
                else {
                    float beta = -copysignf(sqrtf(al * al + n2), al);
                    tau  = (beta - al) / beta;
                    scal = 1.0f / (al - beta);
                }
#pragma unroll
                for (int r = 0; r < 16; r++) {
                    int i = 16 * l + r;
                    float vv;
                    if (i < j) vv = 0.f;
                    else if (i == j) vv = 1.f;
                    else { vv = a[cc][r] * scal; a[cc][r] = vv; }
                    vb[i] = vv;
                }
                if (l == 0) tauv[j] = tau;
            }
        }
        __syncthreads();
        float tau = tauv[j];
        if (tau != 0.f && (4 * w + 3) > j) {
            float vr[16];
#pragma unroll
            for (int r = 0; r < 16; r++) vr[r] = vb[16 * l + r];
#pragma unroll
            for (int c = 0; c < 4; c++) {
                int C = 4 * w + c;
                if (C > j) {
                    float s = 0.f;
#pragma unroll
                    for (int r = 0; r < 16; r++) s += vr[r] * a[c][r];
#pragma unroll
                    for (int o = 16; o; o >>= 1) s += __shfl_xor_sync(0xffffffffu, s, o);
                    float wc = tau * s;
#pragma unroll
                    for (int r = 0; r < 16; r++) a[c][r] -= vr[r] * wc;
                }
            }
        }
    }
    __syncthreads();

    for (int j = 63; j >= 0; j--) {
        int jw = j >> 2, jc = j & 3;
        float tau = tauv[j];
        float* vb = vsh[j & 1];
        if (w == jw) {
#pragma unroll
            for (int cc = 0; cc < 4; cc++) if (cc == jc) {
#pragma unroll
                for (int r = 0; r < 16; r++) {
                    int i = 16 * l + r;
                    float vv;
                    if (i < j) vv = 0.f;
                    else if (i == j) vv = 1.f;
                    else vv = a[cc][r];
                    vb[i] = vv;
                }
            }
        }
        __syncthreads();
        if (tau != 0.f && (4 * w + 3) > j) {
            float vr[16];
#pragma unroll
            for (int r = 0; r < 16; r++) vr[r] = vb[16 * l + r];
#pragma unroll
            for (int c = 0; c < 4; c++) {
                int C = 4 * w + c;
                if (C > j) {
                    float s = 0.f;
#pragma unroll
                    for (int r = 0; r < 16; r++) s += vr[r] * a[c][r];
#pragma unroll
                    for (int o = 16; o; o >>= 1) s += __shfl_xor_sync(0xffffffffu, s, o);
                    float wc = tau * s;
#pragma unroll
                    for (int r = 0; r < 16; r++) a[c][r] -= vr[r] * wc;
                }
            }
        }
        if (w == jw) {
#pragma unroll
            for (int cc = 0; cc < 4; cc++) if (cc == jc) {
#pragma unroll
                for (int r = 0; r < 16; r++) {
                    int i = 16 * l + r;
                    float val;
                    if (i < j) val = 0.f;
                    else if (i == j) val = 1.f - tau;
                    else val = -tau * a[cc][r];
                    a[cc][r] = val;
                }
            }
        }
    }
    __syncthreads();

#pragma unroll
    for (int r = 0; r < 16; r++) {
        float4 v4 = make_float4(a[0][r], a[1][r], a[2][r], a[3][r]);
        *(float4*)(dst + (size_t)(16 * l + r) * 64 + 4 * w) = v4;
    }
}

// ======================= fused 18->6 channel mix + softmax =======================
__global__ __launch_bounds__(512)
void mix_softmax(const float* __restrict__ scale_p, const float* __restrict__ rs_p,
                 const float* __restrict__ gs_p, const float* __restrict__ conv_w,
                 const float* __restrict__ conv_b, float* __restrict__ attn_out)
{
    int bn = blockIdx.x;
    int b = bn >> 9, n = bn & 511;
    int t = threadIdx.x;
    __shared__ float cw[108], cb[6], sq4[6], sca[3];
    __shared__ float red2[16];
    if (t < 108) cw[t] = conv_w[t];
    if (t < 6) { cb[t] = conv_b[t]; sq4[t] = g_qn4[(b * 6 + t) * 512 + n]; }
    if (t == 120) sca[0] = scale_p[0];
    if (t == 121) sca[1] = rs_p[0];
    if (t == 122) sca[2] = gs_p[0];
    __syncthreads();

    float mix[6];
#pragma unroll
    for (int o = 0; o < 6; o++) mix[o] = cb[o];
#pragma unroll
    for (int h = 0; h < 6; h++) {
        size_t base = ((size_t)(b * 6 + h) * 512 + n) * 512 + t;
        float qk = g_qk[base];
        float dd = g_dd[base];
        float kn4 = g_kn4[(b * 6 + h) * 512 + t];
        float eu = qk * sca[0];
        float ri = sqrtf(fmaxf(sq4[h] + kn4 - 2.0f * qk * qk, 0.0f)) * sca[1];
        float gr = dd * dd * sca[2];
#pragma unroll
        for (int o = 0; o < 6; o++)
            mix[o] += cw[o * 18 + h] * eu + cw[o * 18 + 6 + h] * ri + cw[o * 18 + 12 + h] * gr;
    }

    int lane = t & 31, wid = t >> 5;
    for (int o = 0; o < 6; o++) {
        float v = mix[o];
#pragma unroll
        for (int of = 16; of; of >>= 1) v = fmaxf(v, __shfl_xor_sync(0xffffffffu, v, of));
        if (lane == 0) red2[wid] = v;
        __syncthreads();
        if (t < 32) {
            float x = (t < 16) ? red2[t] : -3.4e38f;
#pragma unroll
            for (int of = 8; of; of >>= 1) x = fmaxf(x, __shfl_xor_sync(0xffffffffu, x, of));
            if (t == 0) red2[0] = x;
        }
        __syncthreads();
        float mx = red2[0];
        __syncthreads();
        float e = expf(mix[o] - mx);
        float s = e;
#pragma unroll
        for (int of = 16; of; of >>= 1) s += __shfl_xor_sync(0xffffffffu, s, of);
        if (lane == 0) red2[wid] = s;
        __syncthreads();
        if (t < 32) {
            float x = (t < 16) ? red2[t] : 0.f;
#pragma unroll
            for (int of = 8; of; of >>= 1) x += __shfl_xor_sync(0xffffffffu, x, of);
            if (t == 0) red2[0] = x;
        }
        __syncthreads();
        float r = e / red2[0];
        attn_out[((size_t)(b * 6 + o) * 512 + n) * 512 + t] = r;
        __syncthreads();
    }
}

// ======================= batched attn @ V (tf32 mma), scattered to [B,N,C] =======================
// CTA tile 128x64 (M x N), warp grid 2x4 -> warp tile 64x16. K = 512, k-tile 16.
__global__ __launch_bounds__(256, 2)
void bgemm_av_mma(const float* __restrict__ attn)
{
    __shared__ uint32_t As[128 * 20];
    __shared__ uint32_t Vs[64 * 20];
    int bh = blockIdx.y;
    int m0 = blockIdx.x * 128;
    int b = bh / 6, h = bh - b * 6;
    int t = threadIdx.x;
    int warp = t >> 5, lane = t & 31;
    int g = lane >> 2, tig = lane & 3;
    int wm = warp >> 2, wn = warp & 3;
    int mB = wm * 64, nB = wn * 16;

    const float* Ap = attn + (size_t)bh * NNX * NNX;
    const float* Vp = g_v + (size_t)bh * NNX * HDX;

    float acc[4][2][4];
#pragma unroll
    for (int i = 0; i < 4; i++)
#pragma unroll
        for (int j = 0; j < 2; j++)
#pragma unroll
            for (int v = 0; v < 4; v++) acc[i][j][v] = 0.f;

    int lr = t >> 2;
    int lc = (t & 3) * 4;
    const float* Ap0 = Ap + (size_t)(m0 + lr) * NNX + lc;
    const float* Ap1 = Ap + (size_t)(m0 + 64 + lr) * NNX + lc;
    int vk0 = t >> 6, vn = t & 63;

    float4 rA0 = *(const float4*)(Ap0);
    float4 rA1 = *(const float4*)(Ap1);
    float rV[4];
#pragma unroll
    for (int u = 0; u < 4; u++)
        rV[u] = Vp[(size_t)(vk0 + u * 4) * HDX + vn];

    for (int kt = 0; kt < NNX; kt += 16) {
        {
            uint32_t* as0 = As + lr * 20 + lc;
            uint32_t* as1 = As + (64 + lr) * 20 + lc;
            as0[0] = f2tf32(rA0.x); as0[1] = f2tf32(rA0.y); as0[2] = f2tf32(rA0.z); as0[3] = f2tf32(rA0.w);
            as1[0] = f2tf32(rA1.x); as1[1] = f2tf32(rA1.y); as1[2] = f2tf32(rA1.z); as1[3] = f2tf32(rA1.w);
#pragma unroll
            for (int u = 0; u < 4; u++)
                Vs[vn * 20 + vk0 + u * 4] = f2tf32(rV[u]);
        }
        __syncthreads();
        if (kt + 16 < NNX) {
            rA0 = *(const float4*)(Ap0 + kt + 16);
            rA1 = *(const float4*)(Ap1 + kt + 16);
#pragma unroll
            for (int u = 0; u < 4; u++)
                rV[u] = Vp[(size_t)(kt + 16 + vk0 + u * 4) * HDX + vn];
        }
#pragma unroll
        for (int ks = 0; ks < 16; ks += 8) {
            uint32_t af[4][4], bf[2][2];
#pragma unroll
            for (int i = 0; i < 4; i++) {
                int base = (mB + i * 16 + g) * 20 + ks + tig;
                af[i][0] = As[base];
                af[i][1] = As[base + 8 * 20];
                af[i][2] = As[base + 4];
                af[i][3] = As[base + 8 * 20 + 4];
            }
#pragma unroll
            for (int j = 0; j < 2; j++) {
                int base = (nB + j * 8 + g) * 20 + ks + tig;
                bf[j][0] = Vs[base];
                bf[j][1] = Vs[base + 4];
            }
#pragma unroll
            for (int i = 0; i < 4; i++)
#pragma unroll
                for (int j = 0; j < 2; j++)
                    mma_tf32(acc[i][j][0], acc[i][j][1], acc[i][j][2], acc[i][j][3],
                             af[i][0], af[i][1], af[i][2], af[i][3],
                             bf[j][0], bf[j][1]);
        }
        __syncthreads();
    }

#pragma unroll
    for (int i = 0; i < 4; i++) {
#pragma unroll
        for (int j = 0; j < 2; j++) {
            int r0 = m0 + mB + i * 16 + g;
            int c0 = nB + j * 8 + 2 * tig;
#pragma unroll
            for (int half = 0; half < 2; half++) {
                int m = r0 + half * 8;
                *(float2*)&g_attnv[(size_t)(b * 512 + m) * CCX + h * 64 + c0] =
                    make_float2(acc[i][j][half * 2 + 0], acc[i][j][half * 2 + 1]);
            }
        }
    }
}

// ======================= launch =======================
extern "C" void kernel_launch(void* const* d_in, const int* in_sizes, int n_in,
                              void* d_out, int out_size)
{
    const float* src    = (const float*)d_in[0];
    const float* pre_w  = (const float*)d_in[1];
    const float* pre_b  = (const float*)d_in[2];
    const float* qkv_w  = (const float*)d_in[3];
    const float* qkv_b  = (const float*)d_in[4];
    const float* scale  = (const float*)d_in[5];
    const float* riem   = (const float*)d_in[6];
    const float* grass  = (const float*)d_in[7];
    const float* conv_w = (const float*)d_in[8];
    const float* conv_b = (const float*)d_in[9];
    const float* proj_w = (const float*)d_in[10];
    const float* proj_b = (const float*)d_in[11];
    const float* n1_w   = (const float*)d_in[12];
    const float* n1_b   = (const float*)d_in[13];
    const float* l1_w   = (const float*)d_in[14];
    const float* l1_b   = (const float*)d_in[15];
    const float* l2_w   = (const float*)d_in[16];
    const float* l2_b   = (const float*)d_in[17];
    float* out = (float*)d_out;

    void *p_x, *p_q, *p_k, *p_qgr, *p_kgr, *p_qk, *p_dd, *p_attnv, *p_src1, *p_hff;
    cudaGetSymbolAddress(&p_x, g_x);
    cudaGetSymbolAddress(&p_q, g_q);
    cudaGetSymbolAddress(&p_k, g_k);
    cudaGetSymbolAddress(&p_qgr, g_qgr);
    cudaGetSymbolAddress(&p_kgr, g_kgr);
    cudaGetSymbolAddress(&p_qk, g_qk);
    cudaGetSymbolAddress(&p_dd, g_dd);
    cudaGetSymbolAddress(&p_attnv, g_attnv);
    cudaGetSymbolAddress(&p_src1, g_src1);
    cudaGetSymbolAddress(&p_hff, g_hff);

    // 1. pre-LN
    ln_kernel<<<MTOK, 128>>>(src, pre_w, pre_b, (float*)p_x);
    // 2. QKV projection (tf32 mma), scattered into per-head q/k/v
    mmgemm_abt<EPI_QKV><<<dim3(FFD / 128, MTOK / 128), 256>>>(
        (const float*)p_x, qkv_w, qkv_b, nullptr, nullptr, MTOK, FFD, CCX);
    // 3. row norms^4
    norms_kernel<<<(BHX * NNX + 255) / 256, 256>>>();
    // 4. register-resident Householder QR, q and k in one launch (192 blocks)
    qr_kernel2<<<2 * BHX, 512>>>((const float*)p_q, (float*)p_qgr,
                                 (const float*)p_k, (float*)p_kgr);
    // 5. BOTH score GEMMs in one launch (tf32 mma, 2 CTAs/SM)
    bgemm_nt_mma<<<dim3(4, 4, 2 * BHX), 256>>>(
        (const float*)p_q, (const float*)p_k, (const float*)p_qgr, (const float*)p_kgr,
        (float*)p_qk, (float*)p_dd);
    // 6. fused channel-mix + softmax -> attn output region of d_out
    float* attn_out = out + OUT_ATTN_OFF;
    mix_softmax<<<MTOK, 512>>>(scale, riem, grass, conv_w, conv_b, attn_out);
    // 7. attn @ V (tf32 mma) -> [B,N,C] layout
    bgemm_av_mma<<<dim3(4, BHX), 256>>>(attn_out);
    // 8. output projection + residual with original src (tf32 mma)
    mmgemm_abt<EPI_RESID><<<dim3(CCX / 128, MTOK / 128), 256>>>(
        (const float*)p_attnv, proj_w, proj_b, src, (float*)p_src1, MTOK, CCX, CCX);
    // 9. norm1
    ln_kernel<<<MTOK, 128>>>((const float*)p_src1, n1_w, n1_b, (float*)p_x);
    // 10. FF lin1 + exact GELU (tf32 mma)
    mmgemm_abt<EPI_GELU><<<dim3(FFD / 128, MTOK / 128), 256>>>(
        (const float*)p_x, l1_w, l1_b, nullptr, (float*)p_hff, MTOK, FFD, CCX);
    // 11. FF lin2 + residual -> src part of d_out (tf32 mma)
    mmgemm_abt<EPI_RESID><<<dim3(CCX / 128, MTOK / 128), 256>>>(
        (const float*)p_hff, l2_w, l2_b, (const float*)p_x, out, MTOK, CCX, FFD);

    (void)in_sizes; (void)n_in; (void)out_size;
}

// round 14
// speedup vs baseline: 1.6687x; 1.0703x over previous
#include <cuda_runtime.h>
#include <math.h>
#include <stdint.h>

#define BB 16
#define NNX 512
#define CCX 384
#define HHX 6
#define HDX 64
#define FFD 1152
#define BHX (BB*HHX)        // 96
#define MTOK (BB*NNX)       // 8192
#define OUT_ATTN_OFF ((size_t)MTOK*CCX)   // 3145728

// ---------------- device scratch (no dynamic allocation allowed) ----------------
__device__ float g_x[MTOK*CCX];
__device__ float g_q[BHX*NNX*HDX];
__device__ float g_k[BHX*NNX*HDX];
__device__ float g_v[BHX*NNX*HDX];
__device__ float g_qgr[BHX*NNX*HDX];
__device__ float g_kgr[BHX*NNX*HDX];
__device__ float g_qn4[BHX*NNX];
__device__ float g_kn4[BHX*NNX];
__device__ float g_qk[BHX*NNX*NNX];
__device__ float g_dd[BHX*NNX*NNX];
__device__ float g_attnv[MTOK*CCX];
__device__ float g_src1[MTOK*CCX];
__device__ float g_hff[MTOK*FFD];

// ======================= LayerNorm (row of 384, 128 threads) =======================
__global__ void ln_kernel(const float* __restrict__ in, const float* __restrict__ w,
                          const float* __restrict__ b, float* __restrict__ out)
{
    int row = blockIdx.x;
    int t = threadIdx.x;
    const float* p = in + (size_t)row * CCX;
    float v0 = p[t], v1 = p[t + 128], v2 = p[t + 256];
    __shared__ float sh[4];
    float s = v0 + v1 + v2;
#pragma unroll
    for (int o = 16; o; o >>= 1) s += __shfl_xor_sync(0xffffffffu, s, o);
    if ((t & 31) == 0) sh[t >> 5] = s;
    __syncthreads();
    float mu = (sh[0] + sh[1] + sh[2] + sh[3]) * (1.0f / CCX);
    __syncthreads();
    float d0 = v0 - mu, d1 = v1 - mu, d2 = v2 - mu;
    float s2 = d0 * d0 + d1 * d1 + d2 * d2;
#pragma unroll
    for (int o = 16; o; o >>= 1) s2 += __shfl_xor_sync(0xffffffffu, s2, o);
    if ((t & 31) == 0) sh[t >> 5] = s2;
    __syncthreads();
    float var = (sh[0] + sh[1] + sh[2] + sh[3]) * (1.0f / CCX);
    float r = rsqrtf(var + 1e-5f);
    float* q = out + (size_t)row * CCX;
    q[t]       = d0 * r * w[t]       + b[t];
    q[t + 128] = d1 * r * w[t + 128] + b[t + 128];
    q[t + 256] = d2 * r * w[t + 256] + b[t + 256];
}

// ======================= tf32 helpers =======================
__device__ __forceinline__ uint32_t f2tf32(float x) {
    uint32_t r;
    asm("cvt.rna.tf32.f32 %0, %1;" : "=r"(r) : "f"(x));
    return r;
}

__device__ __forceinline__ void mma_tf32(float& d0, float& d1, float& d2, float& d3,
                                         uint32_t a0, uint32_t a1, uint32_t a2, uint32_t a3,
                                         uint32_t b0, uint32_t b1) {
    asm volatile(
        "mma.sync.aligned.m16n8k8.row.col.f32.tf32.tf32.f32 "
        "{%0,%1,%2,%3}, {%4,%5,%6,%7}, {%8,%9}, {%0,%1,%2,%3};\n"
        : "+f"(d0), "+f"(d1), "+f"(d2), "+f"(d3)
        : "r"(a0), "r"(a1), "r"(a2), "r"(a3), "r"(b0), "r"(b1));
}

// ======================= tf32 mma GEMM: C[M,L] = A[M,K] @ W[L,K]^T + bias =======================
#define EPI_NONE 0
#define EPI_QKV  1
#define EPI_GELU 2
#define EPI_RESID 3

template<int EPI>
__global__ __launch_bounds__(256)
void mmgemm_abt(const float* __restrict__ A, const float* __restrict__ W,
                const float* __restrict__ bias, const float* __restrict__ resid,
                float* __restrict__ C, int M, int L, int K)
{
    __shared__ uint32_t As[128 * 20];
    __shared__ uint32_t Ws[128 * 20];
    int m0 = blockIdx.y * 128;
    int l0 = blockIdx.x * 128;
    int t = threadIdx.x;
    int warp = t >> 5, lane = t & 31;
    int g = lane >> 2, tig = lane & 3;
    int wm = warp >> 2, wn = warp & 3;        // warp grid 2 x 4
    int mB = wm * 64, nB = wn * 32;

    float acc[4][4][4];
#pragma unroll
    for (int i = 0; i < 4; i++)
#pragma unroll
        for (int j = 0; j < 4; j++)
#pragma unroll
            for (int v = 0; v < 4; v++) acc[i][j][v] = 0.f;

    int lr = t >> 2;
    int lc = (t & 3) * 4;
    const float* Ap0 = A + (size_t)(m0 + lr) * K + lc;
    const float* Ap1 = A + (size_t)(m0 + 64 + lr) * K + lc;
    const float* Wp0 = W + (size_t)(l0 + lr) * K + lc;
    const float* Wp1 = W + (size_t)(l0 + 64 + lr) * K + lc;

    float4 rA0 = *(const float4*)(Ap0);
    float4 rA1 = *(const float4*)(Ap1);
    float4 rW0 = *(const float4*)(Wp0);
    float4 rW1 = *(const float4*)(Wp1);

    for (int kt = 0; kt < K; kt += 16) {
        {
            uint32_t* as0 = As + lr * 20 + lc;
            uint32_t* as1 = As + (64 + lr) * 20 + lc;
            uint32_t* ws0 = Ws + lr * 20 + lc;
            uint32_t* ws1 = Ws + (64 + lr) * 20 + lc;
            as0[0] = f2tf32(rA0.x); as0[1] = f2tf32(rA0.y); as0[2] = f2tf32(rA0.z); as0[3] = f2tf32(rA0.w);
            as1[0] = f2tf32(rA1.x); as1[1] = f2tf32(rA1.y); as1[2] = f2tf32(rA1.z); as1[3] = f2tf32(rA1.w);
            ws0[0] = f2tf32(rW0.x); ws0[1] = f2tf32(rW0.y); ws0[2] = f2tf32(rW0.z); ws0[3] = f2tf32(rW0.w);
            ws1[0] = f2tf32(rW1.x); ws1[1] = f2tf32(rW1.y); ws1[2] = f2tf32(rW1.z); ws1[3] = f2tf32(rW1.w);
        }
        __syncthreads();
        if (kt + 16 < K) {
            rA0 = *(const float4*)(Ap0 + kt + 16);
            rA1 = *(const float4*)(Ap1 + kt + 16);
            rW0 = *(const float4*)(Wp0 + kt + 16);
            rW1 = *(const float4*)(Wp1 + kt + 16);
        }
#pragma unroll
        for (int ks = 0; ks < 16; ks += 8) {
            uint32_t af[4][4], bf[4][2];
#pragma unroll
            for (int i = 0; i < 4; i++) {
                int base = (mB + i * 16 + g) * 20 + ks + tig;
                af[i][0] = As[base];
                af[i][1] = As[base + 8 * 20];
                af[i][2] = As[base + 4];
                af[i][3] = As[base + 8 * 20 + 4];
            }
#pragma unroll
            for (int j = 0; j < 4; j++) {
                int base = (nB + j * 8 + g) * 20 + ks + tig;
                bf[j][0] = Ws[base];
                bf[j][1] = Ws[base + 4];
            }
#pragma unroll
            for (int i = 0; i < 4; i++)
#pragma unroll
                for (int j = 0; j < 4; j++)
                    mma_tf32(acc[i][j][0], acc[i][j][1], acc[i][j][2], acc[i][j][3],
                             af[i][0], af[i][1], af[i][2], af[i][3],
                             bf[j][0], bf[j][1]);
        }
        __syncthreads();
    }

#pragma unroll
    for (int i = 0; i < 4; i++) {
#pragma unroll
        for (int j = 0; j < 4; j++) {
            int r0 = m0 + mB + i * 16 + g;
            int c0 = l0 + nB + j * 8 + 2 * tig;
            float b0v = bias[c0], b1v = bias[c0 + 1];
#pragma unroll
            for (int half = 0; half < 2; half++) {
                int row = r0 + half * 8;
                float v0 = acc[i][j][half * 2 + 0] + b0v;
                float v1 = acc[i][j][half * 2 + 1] + b1v;
                if (EPI == EPI_NONE) {
                    *(float2*)&C[(size_t)row * L + c0] = make_float2(v0, v1);
                } else if (EPI == EPI_GELU) {
                    v0 = 0.5f * v0 * (1.0f + erff(v0 * 0.70710678118654752f));
                    v1 = 0.5f * v1 * (1.0f + erff(v1 * 0.70710678118654752f));
                    *(float2*)&C[(size_t)row * L + c0] = make_float2(v0, v1);
                } else if (EPI == EPI_RESID) {
                    const float2 rv = *(const float2*)&resid[(size_t)row * L + c0];
                    *(float2*)&C[(size_t)row * L + c0] = make_float2(v0 + rv.x, v1 + rv.y);
                } else { // QKV scatter
#pragma unroll
                    for (int e = 0; e < 2; e++) {
                        int col = c0 + e;
                        float val = (e == 0) ? v0 : v1;
                        int three = col / 384;
                        int rem = col - three * 384;
                        int h = rem >> 6, d = rem & 63;
                        int bb = row >> 9, n = row & 511;
                        float* dst = (three == 0) ? g_q : ((three == 1) ? g_k : g_v);
                        dst[((size_t)(bb * 6 + h) * 512 + n) * 64 + d] = val;
                    }
                }
            }
        }
    }
}

// ======================= batched NT tf32 GEMM (both score GEMMs in ONE launch) =======================
__global__ __launch_bounds__(256, 2)
void bgemm_nt_mma(const float* __restrict__ Q, const float* __restrict__ Km,
                  const float* __restrict__ Qg, const float* __restrict__ Kg,
                  float* __restrict__ Cqk, float* __restrict__ Cdd)
{
    __shared__ uint32_t As[128 * 20];
    __shared__ uint32_t Ws[128 * 20];
    int z = blockIdx.z;
    int bh = (z < BHX) ? z : (z - BHX);
    const float* X = (z < BHX) ? Q : Qg;
    const float* Y = (z < BHX) ? Km : Kg;
    float* C = (z < BHX) ? Cqk : Cdd;
    int m0 = blockIdx.y * 128;
    int n0 = blockIdx.x * 128;
    int t = threadIdx.x;
    int warp = t >> 5, lane = t & 31;
    int g = lane >> 2, tig = lane & 3;
    int wm = warp >> 2, wn = warp & 3;
    int mB = wm * 64, nB = wn * 32;

    const float* Xb = X + (size_t)bh * NNX * HDX;
    const float* Yb = Y + (size_t)bh * NNX * HDX;

    float acc[4][4][4];
#pragma unroll
    for (int i = 0; i < 4; i++)
#pragma unroll
        for (int j = 0; j < 4; j++)
#pragma unroll
            for (int v = 0; v < 4; v++) acc[i][j][v] = 0.f;

    int lr = t >> 2;
    int lc = (t & 3) * 4;
    const float* Ap0 = Xb + (size_t)(m0 + lr) * HDX + lc;
    const float* Ap1 = Xb + (size_t)(m0 + 64 + lr) * HDX + lc;
    const float* Wp0 = Yb + (size_t)(n0 + lr) * HDX + lc;
    const float* Wp1 = Yb + (size_t)(n0 + 64 + lr) * HDX + lc;

    float4 rA0 = *(const float4*)(Ap0);
    float4 rA1 = *(const float4*)(Ap1);
    float4 rW0 = *(const float4*)(Wp0);
    float4 rW1 = *(const float4*)(Wp1);

    for (int kt = 0; kt < HDX; kt += 16) {
        {
            uint32_t* as0 = As + lr * 20 + lc;
            uint32_t* as1 = As + (64 + lr) * 20 + lc;
            uint32_t* ws0 = Ws + lr * 20 + lc;
            uint32_t* ws1 = Ws + (64 + lr) * 20 + lc;
            as0[0] = f2tf32(rA0.x); as0[1] = f2tf32(rA0.y); as0[2] = f2tf32(rA0.z); as0[3] = f2tf32(rA0.w);
            as1[0] = f2tf32(rA1.x); as1[1] = f2tf32(rA1.y); as1[2] = f2tf32(rA1.z); as1[3] = f2tf32(rA1.w);
            ws0[0] = f2tf32(rW0.x); ws0[1] = f2tf32(rW0.y); ws0[2] = f2tf32(rW0.z); ws0[3] = f2tf32(rW0.w);
            ws1[0] = f2tf32(rW1.x); ws1[1] = f2tf32(rW1.y); ws1[2] = f2tf32(rW1.z); ws1[3] = f2tf32(rW1.w);
        }
        __syncthreads();
        if (kt + 16 < HDX) {
            rA0 = *(const float4*)(Ap0 + kt + 16);
            rA1 = *(const float4*)(Ap1 + kt + 16);
            rW0 = *(const float4*)(Wp0 + kt + 16);
            rW1 = *(const float4*)(Wp1 + kt + 16);
        }
#pragma unroll
        for (int ks = 0; ks < 16; ks += 8) {
            uint32_t af[4][4], bf[4][2];
#pragma unroll
            for (int i = 0; i < 4; i++) {
                int base = (mB + i * 16 + g) * 20 + ks + tig;
                af[i][0] = As[base];
                af[i][1] = As[base + 8 * 20];
                af[i][2] = As[base + 4];
                af[i][3] = As[base + 8 * 20 + 4];
            }
#pragma unroll
            for (int j = 0; j < 4; j++) {
                int base = (nB + j * 8 + g) * 20 + ks + tig;
                bf[j][0] = Ws[base];
                bf[j][1] = Ws[base + 4];
            }
#pragma unroll
            for (int i = 0; i < 4; i++)
#pragma unroll
                for (int j = 0; j < 4; j++)
                    mma_tf32(acc[i][j][0], acc[i][j][1], acc[i][j][2], acc[i][j][3],
                             af[i][0], af[i][1], af[i][2], af[i][3],
                             bf[j][0], bf[j][1]);
        }
        __syncthreads();
    }

    float* Cp = C + (size_t)bh * NNX * NNX;
#pragma unroll
    for (int i = 0; i < 4; i++) {
#pragma unroll
        for (int j = 0; j < 4; j++) {
            int r0 = m0 + mB + i * 16 + g;
            int c0 = n0 + nB + j * 8 + 2 * tig;
#pragma unroll
            for (int half = 0; half < 2; half++) {
                int row = r0 + half * 8;
                *(float2*)&Cp[(size_t)row * NNX + c0] =
                    make_float2(acc[i][j][half * 2 + 0], acc[i][j][half * 2 + 1]);
            }
        }
    }
}

// ======================= per-row squared-norms^2 =======================
__global__ void norms_kernel()
{
    int idx = blockIdx.x * 256 + threadIdx.x;
    if (idx >= BHX * NNX) return;
    const float* pq = g_q + (size_t)idx * 64;
    const float* pk = g_k + (size_t)idx * 64;
    float sq = 0.f, sk = 0.f;
#pragma unroll
    for (int d = 0; d < 64; d++) { sq += pq[d] * pq[d]; sk += pk[d] * pk[d]; }
    g_qn4[idx] = sq * sq;
    g_kn4[idx] = sk * sk;
}

// ======================= register-resident Householder QR (512x64, reduced Q) =======================
// vsh broadcast buffer is stride-17 padded: VIDX(16l+r) = 17l + r, so the 8 lanes
// of each smem phase hit 8 distinct banks (was a 4-way conflict at stride 16).
#define VIDX(i) ((i) + ((i) >> 4))
__global__ __launch_bounds__(512, 1)
void qr_kernel2(const float* __restrict__ X0, float* __restrict__ Q0,
                const float* __restrict__ X1, float* __restrict__ Q1)
{
    int bh = blockIdx.x;
    const float* src = (bh < BHX) ? (X0 + (size_t)bh * 512 * 64)
                                  : (X1 + (size_t)(bh - BHX) * 512 * 64);
    float* dst = (bh < BHX) ? (Q0 + (size_t)bh * 512 * 64)
                            : (Q1 + (size_t)(bh - BHX) * 512 * 64);
    int t = threadIdx.x;
    int w = t >> 5, l = t & 31;
    __shared__ float vsh[2][544];
    __shared__ float tauv[64];

    float a[4][16];
#pragma unroll
    for (int r = 0; r < 16; r++) {
        float4 v4 = *(const float4*)(src + (size_t)(16 * l + r) * 64 + 4 * w);
        a[0][r] = v4.x; a[1][r] = v4.y; a[2][r] = v4.z; a[3][r] = v4.w;
    }

    for (int j = 0; j < 64; j++) {
        int jw = j >> 2, jc = j & 3;
        float* vb = vsh[j & 1];
        if (w == jw) {
#pragma unroll
            for (int cc = 0; cc < 4; cc++) if (cc == jc) {
                float n2 = 0.f, al = 0.f;
#pragma unroll
                for (int r = 0; r < 16; r++) {
                    int i = 16 * l + r;
                    float x = a[cc][r];
                    n2 += (i > j) ? x * x : 0.f;
                    al += (i == j) ? x : 0.f;
                }
#pragma unroll
                for (int o = 16; o; o >>= 1) {
                    n2 += __shfl_xor_sync(0xffffffffu, n2, o);
                    al += __shfl_xor_sync(0xffffffffu, al, o);
                }
                float tau, scal;
                if (n2 == 0.f) { tau = 0.f; scal = 0.f; }
                else {
                    float beta = -copysignf(sqrtf(al * al + n2), al);
                    tau  = (beta - al) / beta;
                    scal = 1.0f / (al - beta);
                }
#pragma unroll
                for (int r = 0; r < 16; r++) {
                    int i = 16 * l + r;
                    float vv;
                    if (i < j) vv = 0.f;
                    else if (i == j) vv = 1.f;
                    else { vv = a[cc][r] * scal; a[cc][r] = vv; }
                    vb[VIDX(i)] = vv;
                }
                if (l == 0) tauv[j] = tau;
            }
        }
        __syncthreads();
        float tau = tauv[j];
        if (tau != 0.f && (4 * w + 3) > j) {
            float vr[16];
#pragma unroll
            for (int r = 0; r < 16; r++) vr[r] = vb[17 * l + r];
#pragma unroll
            for (int c = 0; c < 4; c++) {
                int C = 4 * w + c;
                if (C > j) {
                    float s = 0.f;
#pragma unroll
                    for (int r = 0; r < 16; r++) s += vr[r] * a[c][r];
#pragma unroll
                    for (int o = 16; o; o >>= 1) s += __shfl_xor_sync(0xffffffffu, s, o);
                    float wc = tau * s;
#pragma unroll
                    for (int r = 0; r < 16; r++) a[c][r] -= vr[r] * wc;
                }
            }
        }
    }
    __syncthreads();

    for (int j = 63; j >= 0; j--) {
        int jw = j >> 2, jc = j & 3;
        float tau = tauv[j];
        float* vb = vsh[j & 1];
        if (w == jw) {
#pragma unroll
            for (int cc = 0; cc < 4; cc++) if (cc == jc) {
#pragma unroll
                for (int r = 0; r < 16; r++) {
                    int i = 16 * l + r;
                    float vv;
                    if (i < j) vv = 0.f;
                    else if (i == j) vv = 1.f;
                    else vv = a[cc][r];
                    vb[VIDX(i)] = vv;
                }
            }
        }
        __syncthreads();
        if (tau != 0.f && (4 * w + 3) > j) {
            float vr[16];
#pragma unroll
            for (int r = 0; r < 16; r++) vr[r] = vb[17 * l + r];
#pragma unroll
            for (int c = 0; c < 4; c++) {
                int C = 4 * w + c;
                if (C > j) {
                    float s = 0.f;
#pragma unroll
                    for (int r = 0; r < 16; r++) s += vr[r] * a[c][r];
#pragma unroll
                    for (int o = 16; o; o >>= 1) s += __shfl_xor_sync(0xffffffffu, s, o);
                    float wc = tau * s;
#pragma unroll
                    for (int r = 0; r < 16; r++) a[c][r] -= vr[r] * wc;
                }
            }
        }
        if (w == jw) {
#pragma unroll
            for (int cc = 0; cc < 4; cc++) if (cc == jc) {
#pragma unroll
                for (int r = 0; r < 16; r++) {
                    int i = 16 * l + r;
                    float val;
                    if (i < j) val = 0.f;
                    else if (i == j) val = 1.f - tau;
                    else val = -tau * a[cc][r];
                    a[cc][r] = val;
                }
            }
        }
    }
    __syncthreads();

#pragma unroll
    for (int r = 0; r < 16; r++) {
        float4 v4 = make_float4(a[0][r], a[1][r], a[2][r], a[3][r]);
        *(float4*)(dst + (size_t)(16 * l + r) * 64 + 4 * w) = v4;
    }
}

// ======================= fused 18->6 channel mix + softmax (single-pass reductions) =======================
__global__ __launch_bounds__(512)
void mix_softmax(const float* __restrict__ scale_p, const float* __restrict__ rs_p,
                 const float* __restrict__ gs_p, const float* __restrict__ conv_w,
                 const float* __restrict__ conv_b, float* __restrict__ attn_out)
{
    int bn = blockIdx.x;
    int b = bn >> 9, n = bn & 511;
    int t = threadIdx.x;
    __shared__ float cw[108], cb[6], sq4[6], sca[3];
    __shared__ float red[6 * 16];      // per-warp partials for 6 channels
    __shared__ float gmax[6], gsum[6];
    if (t < 108) cw[t] = conv_w[t];
    if (t < 6) { cb[t] = conv_b[t]; sq4[t] = g_qn4[(b * 6 + t) * 512 + n]; }
    if (t == 120) sca[0] = scale_p[0];
    if (t == 121) sca[1] = rs_p[0];
    if (t == 122) sca[2] = gs_p[0];
    __syncthreads();

    float mix[6];
#pragma unroll
    for (int o = 0; o < 6; o++) mix[o] = cb[o];
#pragma unroll
    for (int h = 0; h < 6; h++) {
        size_t base = ((size_t)(b * 6 + h) * 512 + n) * 512 + t;
        float qk = g_qk[base];
        float dd = g_dd[base];
        float kn4 = g_kn4[(b * 6 + h) * 512 + t];
        float eu = qk * sca[0];
        float ri = sqrtf(fmaxf(sq4[h] + kn4 - 2.0f * qk * qk, 0.0f)) * sca[1];
        float gr = dd * dd * sca[2];
#pragma unroll
        for (int o = 0; o < 6; o++)
            mix[o] += cw[o * 18 + h] * eu + cw[o * 18 + 6 + h] * ri + cw[o * 18 + 12 + h] * gr;
    }

    int lane = t & 31, wid = t >> 5;

    // ---- pass 1: block max for all 6 channels (2 barriers) ----
#pragma unroll
    for (int o = 0; o < 6; o++) {
        float v = mix[o];
#pragma unroll
        for (int of = 16; of; of >>= 1) v = fmaxf(v, __shfl_xor_sync(0xffffffffu, v, of));
        if (lane == 0) red[o * 16 + wid] = v;
    }
    __syncthreads();
    if (t < 96) {      // 6 groups of 16 within warps 0-2, shfl width 16
        int o = t >> 4, idx = t & 15;
        float x = red[o * 16 + idx];
#pragma unroll
        for (int of = 8; of; of >>= 1) x = fmaxf(x, __shfl_xor_sync(0xffffffffu, x, of, 16));
        if (idx == 0) gmax[o] = x;
    }
    __syncthreads();

    // ---- pass 2: exp + block sum for all 6 channels (2 barriers) ----
    float ev[6];
#pragma unroll
    for (int o = 0; o < 6; o++) {
        ev[o] = expf(mix[o] - gmax[o]);
        float s = ev[o];
#pragma unroll
        for (int of = 16; of; of >>= 1) s += __shfl_xor_sync(0xffffffffu, s, of);
        if (lane == 0) red[o * 16 + wid] = s;
    }
    __syncthreads();
    if (t < 96) {
        int o = t >> 4, idx = t & 15;
        float x = red[o * 16 + idx];
#pragma unroll
        for (int of = 8; of; of >>= 1) x += __shfl_xor_sync(0xffffffffu, x, of, 16);
        if (idx == 0) gsum[o] = x;
    }
    __syncthreads();

    // ---- write all 6 channels ----
#pragma unroll
    for (int o = 0; o < 6; o++)
        attn_out[((size_t)(b * 6 + o) * 512 + n) * 512 + t] = ev[o] / gsum[o];
}

// ======================= batched attn @ V (tf32 mma), scattered to [B,N,C] =======================
__global__ __launch_bounds__(256, 2)
void bgemm_av_mma(const float* __restrict__ attn)
{
    __shared__ uint32_t As[128 * 20];
    __shared__ uint32_t Vs[64 * 20];
    int bh = blockIdx.y;
    int m0 = blockIdx.x * 128;
    int b = bh / 6, h = bh - b * 6;
    int t = threadIdx.x;
    int warp = t >> 5, lane = t & 31;
    int g = lane >> 2, tig = lane & 3;
    int wm = warp >> 2, wn = warp & 3;
    int mB = wm * 64, nB = wn * 16;

    const float* Ap = attn + (size_t)bh * NNX * NNX;
    const float* Vp = g_v + (size_t)bh * NNX * HDX;

    float acc[4][2][4];
#pragma unroll
    for (int i = 0; i < 4; i++)
#pragma unroll
        for (int j = 0; j < 2; j++)
#pragma unroll
            for (int v = 0; v < 4; v++) acc[i][j][v] = 0.f;

    int lr = t >> 2;
    int lc = (t & 3) * 4;
    const float* Ap0 = Ap + (size_t)(m0 + lr) * NNX + lc;
    const float* Ap1 = Ap + (size_t)(m0 + 64 + lr) * NNX + lc;
    int vk0 = t >> 6, vn = t & 63;

    float4 rA0 = *(const float4*)(Ap0);
    float4 rA1 = *(const float4*)(Ap1);
    float rV[4];
#pragma unroll
    for (int u = 0; u < 4; u++)
        rV[u] = Vp[(size_t)(vk0 + u * 4) * HDX + vn];

    for (int kt = 0; kt < NNX; kt += 16) {
        {
            uint32_t* as0 = As + lr * 20 + lc;
            uint32_t* as1 = As + (64 + lr) * 20 + lc;
            as0[0] = f2tf32(rA0.x); as0[1] = f2tf32(rA0.y); as0[2] = f2tf32(rA0.z); as0[3] = f2tf32(rA0.w);
            as1[0] = f2tf32(rA1.x); as1[1] = f2tf32(rA1.y); as1[2] = f2tf32(rA1.z); as1[3] = f2tf32(rA1.w);
#pragma unroll
            for (int u = 0; u < 4; u++)
                Vs[vn * 20 + vk0 + u * 4] = f2tf32(rV[u]);
        }
        __syncthreads();
        if (kt + 16 < NNX) {
            rA0 = *(const float4*)(Ap0 + kt + 16);
            rA1 = *(const float4*)(Ap1 + kt + 16);
#pragma unroll
            for (int u = 0; u < 4; u++)
                rV[u] = Vp[(size_t)(kt + 16 + vk0 + u * 4) * HDX + vn];
        }
#pragma unroll
        for (int ks = 0; ks < 16; ks += 8) {
            uint32_t af[4][4], bf[2][2];
#pragma unroll
            for (int i = 0; i < 4; i++) {
                int base = (mB + i * 16 + g) * 20 + ks + tig;
                af[i][0] = As[base];
                af[i][1] = As[base + 8 * 20];
                af[i][2] = As[base + 4];
                af[i][3] = As[base + 8 * 20 + 4];
            }
#pragma unroll
            for (int j = 0; j < 2; j++) {
                int base = (nB + j * 8 + g) * 20 + ks + tig;
                bf[j][0] = Vs[base];
                bf[j][1] = Vs[base + 4];
            }
#pragma unroll
            for (int i = 0; i < 4; i++)
#pragma unroll
                for (int j = 0; j < 2; j++)
                    mma_tf32(acc[i][j][0], acc[i][j][1], acc[i][j][2], acc[i][j][3],
                             af[i][0], af[i][1], af[i][2], af[i][3],
                             bf[j][0], bf[j][1]);
        }
        __syncthreads();
    }

#pragma unroll
    for (int i = 0; i < 4; i++) {
#pragma unroll
        for (int j = 0; j < 2; j++) {
            int r0 = m0 + mB + i * 16 + g;
            int c0 = nB + j * 8 + 2 * tig;
#pragma unroll
            for (int half = 0; half < 2; half++) {
                int m = r0 + half * 8;
                *(float2*)&g_attnv[(size_t)(b * 512 + m) * CCX + h * 64 + c0] =
                    make_float2(acc[i][j][half * 2 + 0], acc[i][j][half * 2 + 1]);
            }
        }
    }
}

// ======================= launch =======================
extern "C" void kernel_launch(void* const* d_in, const int* in_sizes, int n_in,
                              void* d_out, int out_size)
{
    const float* src    = (const float*)d_in[0];
    const float* pre_w  = (const float*)d_in[1];
    const float* pre_b  = (const float*)d_in[2];
    const float* qkv_w  = (const float*)d_in[3];
    const float* qkv_b  = (const float*)d_in[4];
    const float* scale  = (const float*)d_in[5];
    const float* riem   = (const float*)d_in[6];
    const float* grass  = (const float*)d_in[7];
    const float* conv_w = (const float*)d_in[8];
    const float* conv_b = (const float*)d_in[9];
    const float* proj_w = (const float*)d_in[10];
    const float* proj_b = (const float*)d_in[11];
    const float* n1_w   = (const float*)d_in[12];
    const float* n1_b   = (const float*)d_in[13];
    const float* l1_w   = (const float*)d_in[14];
    const float* l1_b   = (const float*)d_in[15];
    const float* l2_w   = (const float*)d_in[16];
    const float* l2_b   = (const float*)d_in[17];
    float* out = (float*)d_out;

    void *p_x, *p_q, *p_k, *p_qgr, *p_kgr, *p_qk, *p_dd, *p_attnv, *p_src1, *p_hff;
    cudaGetSymbolAddress(&p_x, g_x);
    cudaGetSymbolAddress(&p_q, g_q);
    cudaGetSymbolAddress(&p_k, g_k);
    cudaGetSymbolAddress(&p_qgr, g_qgr);
    cudaGetSymbolAddress(&p_kgr, g_kgr);
    cudaGetSymbolAddress(&p_qk, g_qk);
    cudaGetSymbolAddress(&p_dd, g_dd);
    cudaGetSymbolAddress(&p_attnv, g_attnv);
    cudaGetSymbolAddress(&p_src1, g_src1);
    cudaGetSymbolAddress(&p_hff, g_hff);

    // 1. pre-LN
    ln_kernel<<<MTOK, 128>>>(src, pre_w, pre_b, (float*)p_x);
    // 2. QKV projection (tf32 mma), scattered into per-head q/k/v
    mmgemm_abt<EPI_QKV><<<dim3(FFD / 128, MTOK / 128), 256>>>(
        (const float*)p_x, qkv_w, qkv_b, nullptr, nullptr, MTOK, FFD, CCX);
    // 3. row norms^4
    norms_kernel<<<(BHX * NNX + 255) / 256, 256>>>();
    // 4. register-resident Householder QR, q and k in one launch (192 blocks)
    qr_kernel2<<<2 * BHX, 512>>>((const float*)p_q, (float*)p_qgr,
                                 (const float*)p_k, (float*)p_kgr);
    // 5. BOTH score GEMMs in one launch (tf32 mma, 2 CTAs/SM)
    bgemm_nt_mma<<<dim3(4, 4, 2 * BHX), 256>>>(
        (const float*)p_q, (const float*)p_k, (const float*)p_qgr, (const float*)p_kgr,
        (float*)p_qk, (float*)p_dd);
    // 6. fused channel-mix + softmax -> attn output region of d_out
    float* attn_out = out + OUT_ATTN_OFF;
    mix_softmax<<<MTOK, 512>>>(scale, riem, grass, conv_w, conv_b, attn_out);
    // 7. attn @ V (tf32 mma) -> [B,N,C] layout
    bgemm_av_mma<<<dim3(4, BHX), 256>>>(attn_out);
    // 8. output projection + residual with original src (tf32 mma)
    mmgemm_abt<EPI_RESID><<<dim3(CCX / 128, MTOK / 128), 256>>>(
        (const float*)p_attnv, proj_w, proj_b, src, (float*)p_src1, MTOK, CCX, CCX);
    // 9. norm1
    ln_kernel<<<MTOK, 128>>>((const float*)p_src1, n1_w, n1_b, (float*)p_x);
    // 10. FF lin1 + exact GELU (tf32 mma)
    mmgemm_abt<EPI_GELU><<<dim3(FFD / 128, MTOK / 128), 256>>>(
        (const float*)p_x, l1_w, l1_b, nullptr, (float*)p_hff, MTOK, FFD, CCX);
    // 11. FF lin2 + residual -> src part of d_out (tf32 mma)
    mmgemm_abt<EPI_RESID><<<dim3(CCX / 128, MTOK / 128), 256>>>(
        (const float*)p_hff, l2_w, l2_b, (const float*)p_x, out, MTOK, CCX, FFD);

    (void)in_sizes; (void)n_in; (void)out_size;
}

// round 15
// speedup vs baseline: 1.7186x; 1.0299x over previous
#include <cuda_runtime.h>
#include <math.h>
#include <stdint.h>

#define BB 16
#define NNX 512
#define CCX 384
#define HHX 6
#define HDX 64
#define FFD 1152
#define BHX (BB*HHX)        // 96
#define MTOK (BB*NNX)       // 8192
#define OUT_ATTN_OFF ((size_t)MTOK*CCX)   // 3145728

// ---------------- device scratch (no dynamic allocation allowed) ----------------
__device__ float g_x[MTOK*CCX];
__device__ float g_q[BHX*NNX*HDX];
__device__ float g_k[BHX*NNX*HDX];
__device__ float g_v[BHX*NNX*HDX];
__device__ float g_qgr[BHX*NNX*HDX];
__device__ float g_kgr[BHX*NNX*HDX];
__device__ float g_qn4[BHX*NNX];
__device__ float g_kn4[BHX*NNX];
__device__ float g_qk[BHX*NNX*NNX];
__device__ float g_dd[BHX*NNX*NNX];
__device__ float g_attnv[MTOK*CCX];
__device__ float g_src1[MTOK*CCX];
__device__ float g_hff[MTOK*FFD];

// ======================= LayerNorm (row of 384, 128 threads) =======================
__global__ void ln_kernel(const float* __restrict__ in, const float* __restrict__ w,
                          const float* __restrict__ b, float* __restrict__ out)
{
    int row = blockIdx.x;
    int t = threadIdx.x;
    const float* p = in + (size_t)row * CCX;
    float v0 = p[t], v1 = p[t + 128], v2 = p[t + 256];
    __shared__ float sh[4];
    float s = v0 + v1 + v2;
#pragma unroll
    for (int o = 16; o; o >>= 1) s += __shfl_xor_sync(0xffffffffu, s, o);
    if ((t & 31) == 0) sh[t >> 5] = s;
    __syncthreads();
    float mu = (sh[0] + sh[1] + sh[2] + sh[3]) * (1.0f / CCX);
    __syncthreads();
    float d0 = v0 - mu, d1 = v1 - mu, d2 = v2 - mu;
    float s2 = d0 * d0 + d1 * d1 + d2 * d2;
#pragma unroll
    for (int o = 16; o; o >>= 1) s2 += __shfl_xor_sync(0xffffffffu, s2, o);
    if ((t & 31) == 0) sh[t >> 5] = s2;
    __syncthreads();
    float var = (sh[0] + sh[1] + sh[2] + sh[3]) * (1.0f / CCX);
    float r = rsqrtf(var + 1e-5f);
    float* q = out + (size_t)row * CCX;
    q[t]       = d0 * r * w[t]       + b[t];
    q[t + 128] = d1 * r * w[t + 128] + b[t + 128];
    q[t + 256] = d2 * r * w[t + 256] + b[t + 256];
}

// ======================= tf32 helpers =======================
__device__ __forceinline__ uint32_t f2tf32(float x) {
    uint32_t r;
    asm("cvt.rna.tf32.f32 %0, %1;" : "=r"(r) : "f"(x));
    return r;
}

__device__ __forceinline__ void mma_tf32(float& d0, float& d1, float& d2, float& d3,
                                         uint32_t a0, uint32_t a1, uint32_t a2, uint32_t a3,
                                         uint32_t b0, uint32_t b1) {
    asm volatile(
        "mma.sync.aligned.m16n8k8.row.col.f32.tf32.tf32.f32 "
        "{%0,%1,%2,%3}, {%4,%5,%6,%7}, {%8,%9}, {%0,%1,%2,%3};\n"
        : "+f"(d0), "+f"(d1), "+f"(d2), "+f"(d3)
        : "r"(a0), "r"(a1), "r"(a2), "r"(a3), "r"(b0), "r"(b1));
}

// ======================= tf32 mma GEMM: C[M,L] = A[M,K] @ W[L,K]^T + bias =======================
// Double-buffered smem (one barrier per k-tile), 2 CTAs/SM.
#define EPI_NONE 0
#define EPI_QKV  1
#define EPI_GELU 2
#define EPI_RESID 3

template<int EPI>
__global__ __launch_bounds__(256, 2)
void mmgemm_abt(const float* __restrict__ A, const float* __restrict__ W,
                const float* __restrict__ bias, const float* __restrict__ resid,
                float* __restrict__ C, int M, int L, int K)
{
    __shared__ uint32_t As[2][128 * 20];
    __shared__ uint32_t Ws[2][128 * 20];
    int m0 = blockIdx.y * 128;
    int l0 = blockIdx.x * 128;
    int t = threadIdx.x;
    int warp = t >> 5, lane = t & 31;
    int g = lane >> 2, tig = lane & 3;
    int wm = warp >> 2, wn = warp & 3;        // warp grid 2 x 4
    int mB = wm * 64, nB = wn * 32;

    float acc[4][4][4];
#pragma unroll
    for (int i = 0; i < 4; i++)
#pragma unroll
        for (int j = 0; j < 4; j++)
#pragma unroll
            for (int v = 0; v < 4; v++) acc[i][j][v] = 0.f;

    int lr = t >> 2;
    int lc = (t & 3) * 4;
    const float* Ap0 = A + (size_t)(m0 + lr) * K + lc;
    const float* Ap1 = A + (size_t)(m0 + 64 + lr) * K + lc;
    const float* Wp0 = W + (size_t)(l0 + lr) * K + lc;
    const float* Wp1 = W + (size_t)(l0 + 64 + lr) * K + lc;

    float4 rA0 = *(const float4*)(Ap0);
    float4 rA1 = *(const float4*)(Ap1);
    float4 rW0 = *(const float4*)(Wp0);
    float4 rW1 = *(const float4*)(Wp1);

    // stage k-tile 0 into buffer 0
    {
        uint32_t* as0 = As[0] + lr * 20 + lc;
        uint32_t* as1 = As[0] + (64 + lr) * 20 + lc;
        uint32_t* ws0 = Ws[0] + lr * 20 + lc;
        uint32_t* ws1 = Ws[0] + (64 + lr) * 20 + lc;
        as0[0] = f2tf32(rA0.x); as0[1] = f2tf32(rA0.y); as0[2] = f2tf32(rA0.z); as0[3] = f2tf32(rA0.w);
        as1[0] = f2tf32(rA1.x); as1[1] = f2tf32(rA1.y); as1[2] = f2tf32(rA1.z); as1[3] = f2tf32(rA1.w);
        ws0[0] = f2tf32(rW0.x); ws0[1] = f2tf32(rW0.y); ws0[2] = f2tf32(rW0.z); ws0[3] = f2tf32(rW0.w);
        ws1[0] = f2tf32(rW1.x); ws1[1] = f2tf32(rW1.y); ws1[2] = f2tf32(rW1.z); ws1[3] = f2tf32(rW1.w);
    }
    __syncthreads();

    int cur = 0;
    for (int kt = 0; kt < K; kt += 16) {
        bool more = (kt + 16 < K);
        if (more) {
            rA0 = *(const float4*)(Ap0 + kt + 16);
            rA1 = *(const float4*)(Ap1 + kt + 16);
            rW0 = *(const float4*)(Wp0 + kt + 16);
            rW1 = *(const float4*)(Wp1 + kt + 16);
        }
        const uint32_t* Ab = As[cur];
        const uint32_t* Wb = Ws[cur];
#pragma unroll
        for (int ks = 0; ks < 16; ks += 8) {
            uint32_t af[4][4], bf[4][2];
#pragma unroll
            for (int i = 0; i < 4; i++) {
                int base = (mB + i * 16 + g) * 20 + ks + tig;
                af[i][0] = Ab[base];
                af[i][1] = Ab[base + 8 * 20];
                af[i][2] = Ab[base + 4];
                af[i][3] = Ab[base + 8 * 20 + 4];
            }
#pragma unroll
            for (int j = 0; j < 4; j++) {
                int base = (nB + j * 8 + g) * 20 + ks + tig;
                bf[j][0] = Wb[base];
                bf[j][1] = Wb[base + 4];
            }
#pragma unroll
            for (int i = 0; i < 4; i++)
#pragma unroll
                for (int j = 0; j < 4; j++)
                    mma_tf32(acc[i][j][0], acc[i][j][1], acc[i][j][2], acc[i][j][3],
                             af[i][0], af[i][1], af[i][2], af[i][3],
                             bf[j][0], bf[j][1]);
        }
        if (more) {
            int nxt = cur ^ 1;
            uint32_t* as0 = As[nxt] + lr * 20 + lc;
            uint32_t* as1 = As[nxt] + (64 + lr) * 20 + lc;
            uint32_t* ws0 = Ws[nxt] + lr * 20 + lc;
            uint32_t* ws1 = Ws[nxt] + (64 + lr) * 20 + lc;
            as0[0] = f2tf32(rA0.x); as0[1] = f2tf32(rA0.y); as0[2] = f2tf32(rA0.z); as0[3] = f2tf32(rA0.w);
            as1[0] = f2tf32(rA1.x); as1[1] = f2tf32(rA1.y); as1[2] = f2tf32(rA1.z); as1[3] = f2tf32(rA1.w);
            ws0[0] = f2tf32(rW0.x); ws0[1] = f2tf32(rW0.y); ws0[2] = f2tf32(rW0.z); ws0[3] = f2tf32(rW0.w);
            ws1[0] = f2tf32(rW1.x); ws1[1] = f2tf32(rW1.y); ws1[2] = f2tf32(rW1.z); ws1[3] = f2tf32(rW1.w);
            __syncthreads();
            cur = nxt;
        }
    }

#pragma unroll
    for (int i = 0; i < 4; i++) {
#pragma unroll
        for (int j = 0; j < 4; j++) {
            int r0 = m0 + mB + i * 16 + g;
            int c0 = l0 + nB + j * 8 + 2 * tig;
            float b0v = bias[c0], b1v = bias[c0 + 1];
#pragma unroll
            for (int half = 0; half < 2; half++) {
                int row = r0 + half * 8;
                float v0 = acc[i][j][half * 2 + 0] + b0v;
                float v1 = acc[i][j][half * 2 + 1] + b1v;
                if (EPI == EPI_NONE) {
                    *(float2*)&C[(size_t)row * L + c0] = make_float2(v0, v1);
                } else if (EPI == EPI_GELU) {
                    v0 = 0.5f * v0 * (1.0f + erff(v0 * 0.70710678118654752f));
                    v1 = 0.5f * v1 * (1.0f + erff(v1 * 0.70710678118654752f));
                    *(float2*)&C[(size_t)row * L + c0] = make_float2(v0, v1);
                } else if (EPI == EPI_RESID) {
                    const float2 rv = *(const float2*)&resid[(size_t)row * L + c0];
                    *(float2*)&C[(size_t)row * L + c0] = make_float2(v0 + rv.x, v1 + rv.y);
                } else { // QKV scatter
#pragma unroll
                    for (int e = 0; e < 2; e++) {
                        int col = c0 + e;
                        float val = (e == 0) ? v0 : v1;
                        int three = col / 384;
                        int rem = col - three * 384;
                        int h = rem >> 6, d = rem & 63;
                        int bb = row >> 9, n = row & 511;
                        float* dst = (three == 0) ? g_q : ((three == 1) ? g_k : g_v);
                        dst[((size_t)(bb * 6 + h) * 512 + n) * 64 + d] = val;
                    }
                }
            }
        }
    }
}

// ======================= batched NT tf32 GEMM (both score GEMMs in ONE launch) =======================
__global__ __launch_bounds__(256, 2)
void bgemm_nt_mma(const float* __restrict__ Q, const float* __restrict__ Km,
                  const float* __restrict__ Qg, const float* __restrict__ Kg,
                  float* __restrict__ Cqk, float* __restrict__ Cdd)
{
    __shared__ uint32_t As[128 * 20];
    __shared__ uint32_t Ws[128 * 20];
    int z = blockIdx.z;
    int bh = (z < BHX) ? z : (z - BHX);
    const float* X = (z < BHX) ? Q : Qg;
    const float* Y = (z < BHX) ? Km : Kg;
    float* C = (z < BHX) ? Cqk : Cdd;
    int m0 = blockIdx.y * 128;
    int n0 = blockIdx.x * 128;
    int t = threadIdx.x;
    int warp = t >> 5, lane = t & 31;
    int g = lane >> 2, tig = lane & 3;
    int wm = warp >> 2, wn = warp & 3;
    int mB = wm * 64, nB = wn * 32;

    const float* Xb = X + (size_t)bh * NNX * HDX;
    const float* Yb = Y + (size_t)bh * NNX * HDX;

    float acc[4][4][4];
#pragma unroll
    for (int i = 0; i < 4; i++)
#pragma unroll
        for (int j = 0; j < 4; j++)
#pragma unroll
            for (int v = 0; v < 4; v++) acc[i][j][v] = 0.f;

    int lr = t >> 2;
    int lc = (t & 3) * 4;
    const float* Ap0 = Xb + (size_t)(m0 + lr) * HDX + lc;
    const float* Ap1 = Xb + (size_t)(m0 + 64 + lr) * HDX + lc;
    const float* Wp0 = Yb + (size_t)(n0 + lr) * HDX + lc;
    const float* Wp1 = Yb + (size_t)(n0 + 64 + lr) * HDX + lc;

    float4 rA0 = *(const float4*)(Ap0);
    float4 rA1 = *(const float4*)(Ap1);
    float4 rW0 = *(const float4*)(Wp0);
    float4 rW1 = *(const float4*)(Wp1);

    for (int kt = 0; kt < HDX; kt += 16) {
        {
            uint32_t* as0 = As + lr * 20 + lc;
            uint32_t* as1 = As + (64 + lr) * 20 + lc;
            uint32_t* ws0 = Ws + lr * 20 + lc;
            uint32_t* ws1 = Ws + (64 + lr) * 20 + lc;
            as0[0] = f2tf32(rA0.x); as0[1] = f2tf32(rA0.y); as0[2] = f2tf32(rA0.z); as0[3] = f2tf32(rA0.w);
            as1[0] = f2tf32(rA1.x); as1[1] = f2tf32(rA1.y); as1[2] = f2tf32(rA1.z); as1[3] = f2tf32(rA1.w);
            ws0[0] = f2tf32(rW0.x); ws0[1] = f2tf32(rW0.y); ws0[2] = f2tf32(rW0.z); ws0[3] = f2tf32(rW0.w);
            ws1[0] = f2tf32(rW1.x); ws1[1] = f2tf32(rW1.y); ws1[2] = f2tf32(rW1.z); ws1[3] = f2tf32(rW1.w);
        }
        __syncthreads();
        if (kt + 16 < HDX) {
            rA0 = *(const float4*)(Ap0 + kt + 16);
            rA1 = *(const float4*)(Ap1 + kt + 16);
            rW0 = *(const float4*)(Wp0 + kt + 16);
            rW1 = *(const float4*)(Wp1 + kt + 16);
        }
#pragma unroll
        for (int ks = 0; ks < 16; ks += 8) {
            uint32_t af[4][4], bf[4][2];
#pragma unroll
            for (int i = 0; i < 4; i++) {
                int base = (mB + i * 16 + g) * 20 + ks + tig;
                af[i][0] = As[base];
                af[i][1] = As[base + 8 * 20];
                af[i][2] = As[base + 4];
                af[i][3] = As[base + 8 * 20 + 4];
            }
#pragma unroll
            for (int j = 0; j < 4; j++) {
                int base = (nB + j * 8 + g) * 20 + ks + tig;
                bf[j][0] = Ws[base];
                bf[j][1] = Ws[base + 4];
            }
#pragma unroll
            for (int i = 0; i < 4; i++)
#pragma unroll
                for (int j = 0; j < 4; j++)
                    mma_tf32(acc[i][j][0], acc[i][j][1], acc[i][j][2], acc[i][j][3],
                             af[i][0], af[i][1], af[i][2], af[i][3],
                             bf[j][0], bf[j][1]);
        }
        __syncthreads();
    }

    float* Cp = C + (size_t)bh * NNX * NNX;
#pragma unroll
    for (int i = 0; i < 4; i++) {
#pragma unroll
        for (int j = 0; j < 4; j++) {
            int r0 = m0 + mB + i * 16 + g;
            int c0 = n0 + nB + j * 8 + 2 * tig;
#pragma unroll
            for (int half = 0; half < 2; half++) {
                int row = r0 + half * 8;
                *(float2*)&Cp[(size_t)row * NNX + c0] =
                    make_float2(acc[i][j][half * 2 + 0], acc[i][j][half * 2 + 1]);
            }
        }
    }
}

// ======================= per-row squared-norms^2 =======================
__global__ void norms_kernel()
{
    int idx = blockIdx.x * 256 + threadIdx.x;
    if (idx >= BHX * NNX) return;
    const float* pq = g_q + (size_t)idx * 64;
    const float* pk = g_k + (size_t)idx * 64;
    float sq = 0.f, sk = 0.f;
#pragma unroll
    for (int d = 0; d < 64; d++) { sq += pq[d] * pq[d]; sk += pk[d] * pk[d]; }
    g_qn4[idx] = sq * sq;
    g_kn4[idx] = sk * sk;
}

// ======================= register-resident Householder QR (512x64, reduced Q) =======================
#define VIDX(i) ((i) + ((i) >> 4))
__global__ __launch_bounds__(512, 1)
void qr_kernel2(const float* __restrict__ X0, float* __restrict__ Q0,
                const float* __restrict__ X1, float* __restrict__ Q1)
{
    int bh = blockIdx.x;
    const float* src = (bh < BHX) ? (X0 + (size_t)bh * 512 * 64)
                                  : (X1 + (size_t)(bh - BHX) * 512 * 64);
    float* dst = (bh < BHX) ? (Q0 + (size_t)bh * 512 * 64)
                            : (Q1 + (size_t)(bh - BHX) * 512 * 64);
    int t = threadIdx.x;
    int w = t >> 5, l = t & 31;
    __shared__ float vsh[2][544];
    __shared__ float tauv[64];

    float a[4][16];
#pragma unroll
    for (int r = 0; r < 16; r++) {
        float4 v4 = *(const float4*)(src + (size_t)(16 * l + r) * 64 + 4 * w);
        a[0][r] = v4.x; a[1][r] = v4.y; a[2][r] = v4.z; a[3][r] = v4.w;
    }

    for (int j = 0; j < 64; j++) {
        int jw = j >> 2, jc = j & 3;
        float* vb = vsh[j & 1];
        if (w == jw) {
#pragma unroll
            for (int cc = 0; cc < 4; cc++) if (cc == jc) {
                float n2 = 0.f, al = 0.f;
#pragma unroll
                for (int r = 0; r < 16; r++) {
                    int i = 16 * l + r;
                    float x = a[cc][r];
                    n2 += (i > j) ? x * x : 0.f;
                    al += (i == j) ? x : 0.f;
                }
#pragma unroll
                for (int o = 16; o; o >>= 1) {
                    n2 += __shfl_xor_sync(0xffffffffu, n2, o);
                    al += __shfl_xor_sync(0xffffffffu, al, o);
                }
                float tau, scal;
                if (n2 == 0.f) { tau = 0.f; scal = 0.f; }
                else {
                    float beta = -copysignf(sqrtf(al * al + n2), al);
                    tau  = (beta - al) / beta;
                    scal = 1.0f / (al - beta);
                }
#pragma unroll
                for (int r = 0; r < 16; r++) {
                    int i = 16 * l + r;
                    float vv;
                    if (i < j) vv = 0.f;
                    else if (i == j) vv = 1.f;
                    else { vv = a[cc][r] * scal; a[cc][r] = vv; }
                    vb[VIDX(i)] = vv;
                }
                if (l == 0) tauv[j] = tau;
            }
        }
        __syncthreads();
        float tau = tauv[j];
        if (tau != 0.f && (4 * w + 3) > j) {
            float vr[16];
#pragma unroll
            for (int r = 0; r < 16; r++) vr[r] = vb[17 * l + r];
#pragma unroll
            for (int c = 0; c < 4; c++) {
                int C = 4 * w + c;
                if (C > j) {
                    float s = 0.f;
#pragma unroll
                    for (int r = 0; r < 16; r++) s += vr[r] * a[c][r];
#pragma unroll
                    for (int o = 16; o; o >>= 1) s += __shfl_xor_sync(0xffffffffu, s, o);
                    float wc = tau * s;
#pragma unroll
                    for (int r = 0; r < 16; r++) a[c][r] -= vr[r] * wc;
                }
            }
        }
    }
    __syncthreads();

    for (int j = 63; j >= 0; j--) {
        int jw = j >> 2, jc = j & 3;
        float tau = tauv[j];
        float* vb = vsh[j & 1];
        if (w == jw) {
#pragma unroll
            for (int cc = 0; cc < 4; cc++) if (cc == jc) {
#pragma unroll
                for (int r = 0; r < 16; r++) {
                    int i = 16 * l + r;
                    float vv;
                    if (i < j) vv = 0.f;
                    else if (i == j) vv = 1.f;
                    else vv = a[cc][r];
                    vb[VIDX(i)] = vv;
                }
            }
        }
        __syncthreads();
        if (tau != 0.f && (4 * w + 3) > j) {
            float vr[16];
#pragma unroll
            for (int r = 0; r < 16; r++) vr[r] = vb[17 * l + r];
#pragma unroll
            for (int c = 0; c < 4; c++) {
                int C = 4 * w + c;
                if (C > j) {
                    float s = 0.f;
#pragma unroll
                    for (int r = 0; r < 16; r++) s += vr[r] * a[c][r];
#pragma unroll
                    for (int o = 16; o; o >>= 1) s += __shfl_xor_sync(0xffffffffu, s, o);
                    float wc = tau * s;
#pragma unroll
                    for (int r = 0; r < 16; r++) a[c][r] -= vr[r] * wc;
                }
            }
        }
        if (w == jw) {
#pragma unroll
            for (int cc = 0; cc < 4; cc++) if (cc == jc) {
#pragma unroll
                for (int r = 0; r < 16; r++) {
                    int i = 16 * l + r;
                    float val;
                    if (i < j) val = 0.f;
                    else if (i == j) val = 1.f - tau;
                    else val = -tau * a[cc][r];
                    a[cc][r] = val;
                }
            }
        }
    }
    __syncthreads();

#pragma unroll
    for (int r = 0; r < 16; r++) {
        float4 v4 = make_float4(a[0][r], a[1][r], a[2][r], a[3][r]);
        *(float4*)(dst + (size_t)(16 * l + r) * 64 + 4 * w) = v4;
    }
}

// ======================= fused 18->6 channel mix + softmax (single-pass reductions) =======================
__global__ __launch_bounds__(512)
void mix_softmax(const float* __restrict__ scale_p, const float* __restrict__ rs_p,
                 const float* __restrict__ gs_p, const float* __restrict__ conv_w,
                 const float* __restrict__ conv_b, float* __restrict__ attn_out)
{
    int bn = blockIdx.x;
    int b = bn >> 9, n = bn & 511;
    int t = threadIdx.x;
    __shared__ float cw[108], cb[6], sq4[6], sca[3];
    __shared__ float red[6 * 16];
    __shared__ float gmax[6], gsum[6];
    if (t < 108) cw[t] = conv_w[t];
    if (t < 6) { cb[t] = conv_b[t]; sq4[t] = g_qn4[(b * 6 + t) * 512 + n]; }
    if (t == 120) sca[0] = scale_p[0];
    if (t == 121) sca[1] = rs_p[0];
    if (t == 122) sca[2] = gs_p[0];
    __syncthreads();

    float mix[6];
#pragma unroll
    for (int o = 0; o < 6; o++) mix[o] = cb[o];
#pragma unroll
    for (int h = 0; h < 6; h++) {
        size_t base = ((size_t)(b * 6 + h) * 512 + n) * 512 + t;
        float qk = g_qk[base];
        float dd = g_dd[base];
        float kn4 = g_kn4[(b * 6 + h) * 512 + t];
        float eu = qk * sca[0];
        float ri = sqrtf(fmaxf(sq4[h] + kn4 - 2.0f * qk * qk, 0.0f)) * sca[1];
        float gr = dd * dd * sca[2];
#pragma unroll
        for (int o = 0; o < 6; o++)
            mix[o] += cw[o * 18 + h] * eu + cw[o * 18 + 6 + h] * ri + cw[o * 18 + 12 + h] * gr;
    }

    int lane = t & 31, wid = t >> 5;

#pragma unroll
    for (int o = 0; o < 6; o++) {
        float v = mix[o];
#pragma unroll
        for (int of = 16; of; of >>= 1) v = fmaxf(v, __shfl_xor_sync(0xffffffffu, v, of));
        if (lane == 0) red[o * 16 + wid] = v;
    }
    __syncthreads();
    if (t < 96) {
        int o = t >> 4, idx = t & 15;
        float x = red[o * 16 + idx];
#pragma unroll
        for (int of = 8; of; of >>= 1) x = fmaxf(x, __shfl_xor_sync(0xffffffffu, x, of, 16));
        if (idx == 0) gmax[o] = x;
    }
    __syncthreads();

    float ev[6];
#pragma unroll
    for (int o = 0; o < 6; o++) {
        ev[o] = expf(mix[o] - gmax[o]);
        float s = ev[o];
#pragma unroll
        for (int of = 16; of; of >>= 1) s += __shfl_xor_sync(0xffffffffu, s, of);
        if (lane == 0) red[o * 16 + wid] = s;
    }
    __syncthreads();
    if (t < 96) {
        int o = t >> 4, idx = t & 15;
        float x = red[o * 16 + idx];
#pragma unroll
        for (int of = 8; of; of >>= 1) x += __shfl_xor_sync(0xffffffffu, x, of, 16);
        if (idx == 0) gsum[o] = x;
    }
    __syncthreads();

#pragma unroll
    for (int o = 0; o < 6; o++)
        attn_out[((size_t)(b * 6 + o) * 512 + n) * 512 + t] = ev[o] / gsum[o];
}

// ======================= batched attn @ V (tf32 mma), scattered to [B,N,C] =======================
__global__ __launch_bounds__(256, 2)
void bgemm_av_mma(const float* __restrict__ attn)
{
    __shared__ uint32_t As[128 * 20];
    __shared__ uint32_t Vs[64 * 20];
    int bh = blockIdx.y;
    int m0 = blockIdx.x * 128;
    int b = bh / 6, h = bh - b * 6;
    int t = threadIdx.x;
    int warp = t >> 5, lane = t & 31;
    int g = lane >> 2, tig = lane & 3;
    int wm = warp >> 2, wn = warp & 3;
    int mB = wm * 64, nB = wn * 16;

    const float* Ap = attn + (size_t)bh * NNX * NNX;
    const float* Vp = g_v + (size_t)bh * NNX * HDX;

    float acc[4][2][4];
#pragma unroll
    for (int i = 0; i < 4; i++)
#pragma unroll
        for (int j = 0; j < 2; j++)
#pragma unroll
            for (int v = 0; v < 4; v++) acc[i][j][v] = 0.f;

    int lr = t >> 2;
    int lc = (t & 3) * 4;
    const float* Ap0 = Ap + (size_t)(m0 + lr) * NNX + lc;
    const float* Ap1 = Ap + (size_t)(m0 + 64 + lr) * NNX + lc;
    int vk0 = t >> 6, vn = t & 63;

    float4 rA0 = *(const float4*)(Ap0);
    float4 rA1 = *(const float4*)(Ap1);
    float rV[4];
#pragma unroll
    for (int u = 0; u < 4; u++)
        rV[u] = Vp[(size_t)(vk0 + u * 4) * HDX + vn];

    for (int kt = 0; kt < NNX; kt += 16) {
        {
            uint32_t* as0 = As + lr * 20 + lc;
            uint32_t* as1 = As + (64 + lr) * 20 + lc;
            as0[0] = f2tf32(rA0.x); as0[1] = f2tf32(rA0.y); as0[2] = f2tf32(rA0.z); as0[3] = f2tf32(rA0.w);
            as1[0] = f2tf32(rA1.x); as1[1] = f2tf32(rA1.y); as1[2] = f2tf32(rA1.z); as1[3] = f2tf32(rA1.w);
#pragma unroll
            for (int u = 0; u < 4; u++)
                Vs[vn * 20 + vk0 + u * 4] = f2tf32(rV[u]);
        }
        __syncthreads();
        if (kt + 16 < NNX) {
            rA0 = *(const float4*)(Ap0 + kt + 16);
            rA1 = *(const float4*)(Ap1 + kt + 16);
#pragma unroll
            for (int u = 0; u < 4; u++)
                rV[u] = Vp[(size_t)(kt + 16 + vk0 + u * 4) * HDX + vn];
        }
#pragma unroll
        for (int ks = 0; ks < 16; ks += 8) {
            uint32_t af[4][4], bf[2][2];
#pragma unroll
            for (int i = 0; i < 4; i++) {
                int base = (mB + i * 16 + g) * 20 + ks + tig;
                af[i][0] = As[base];
                af[i][1] = As[base + 8 * 20];
                af[i][2] = As[base + 4];
                af[i][3] = As[base + 8 * 20 + 4];
            }
#pragma unroll
            for (int j = 0; j < 2; j++) {
                int base = (nB + j * 8 + g) * 20 + ks + tig;
                bf[j][0] = Vs[base];
                bf[j][1] = Vs[base + 4];
            }
#pragma unroll
            for (int i = 0; i < 4; i++)
#pragma unroll
                for (int j = 0; j < 2; j++)
                    mma_tf32(acc[i][j][0], acc[i][j][1], acc[i][j][2], acc[i][j][3],
                             af[i][0], af[i][1], af[i][2], af[i][3],
                             bf[j][0], bf[j][1]);
        }
        __syncthreads();
    }

#pragma unroll
    for (int i = 0; i < 4; i++) {
#pragma unroll
        for (int j = 0; j < 2; j++) {
            int r0 = m0 + mB + i * 16 + g;
            int c0 = nB + j * 8 + 2 * tig;
#pragma unroll
            for (int half = 0; half < 2; half++) {
                int m = r0 + half * 8;
                *(float2*)&g_attnv[(size_t)(b * 512 + m) * CCX + h * 64 + c0] =
                    make_float2(acc[i][j][half * 2 + 0], acc[i][j][half * 2 + 1]);
            }
        }
    }
}

// ======================= launch =======================
extern "C" void kernel_launch(void* const* d_in, const int* in_sizes, int n_in,
                              void* d_out, int out_size)
{
    const float* src    = (const float*)d_in[0];
    const float* pre_w  = (const float*)d_in[1];
    const float* pre_b  = (const float*)d_in[2];
    const float* qkv_w  = (const float*)d_in[3];
    const float* qkv_b  = (const float*)d_in[4];
    const float* scale  = (const float*)d_in[5];
    const float* riem   = (const float*)d_in[6];
    const float* grass  = (const float*)d_in[7];
    const float* conv_w = (const float*)d_in[8];
    const float* conv_b = (const float*)d_in[9];
    const float* proj_w = (const float*)d_in[10];
    const float* proj_b = (const float*)d_in[11];
    const float* n1_w   = (const float*)d_in[12];
    const float* n1_b   = (const float*)d_in[13];
    const float* l1_w   = (const float*)d_in[14];
    const float* l1_b   = (const float*)d_in[15];
    const float* l2_w   = (const float*)d_in[16];
    const float* l2_b   = (const float*)d_in[17];
    float* out = (float*)d_out;

    void *p_x, *p_q, *p_k, *p_qgr, *p_kgr, *p_qk, *p_dd, *p_attnv, *p_src1, *p_hff;
    cudaGetSymbolAddress(&p_x, g_x);
    cudaGetSymbolAddress(&p_q, g_q);
    cudaGetSymbolAddress(&p_k, g_k);
    cudaGetSymbolAddress(&p_qgr, g_qgr);
    cudaGetSymbolAddress(&p_kgr, g_kgr);
    cudaGetSymbolAddress(&p_qk, g_qk);
    cudaGetSymbolAddress(&p_dd, g_dd);
    cudaGetSymbolAddress(&p_attnv, g_attnv);
    cudaGetSymbolAddress(&p_src1, g_src1);
    cudaGetSymbolAddress(&p_hff, g_hff);

    // 1. pre-LN
    ln_kernel<<<MTOK, 128>>>(src, pre_w, pre_b, (float*)p_x);
    // 2. QKV projection (tf32 mma), scattered into per-head q/k/v
    mmgemm_abt<EPI_QKV><<<dim3(FFD / 128, MTOK / 128), 256>>>(
        (const float*)p_x, qkv_w, qkv_b, nullptr, nullptr, MTOK, FFD, CCX);
    // 3. row norms^4
    norms_kernel<<<(BHX * NNX + 255) / 256, 256>>>();
    // 4. register-resident Householder QR, q and k in one launch (192 blocks)
    qr_kernel2<<<2 * BHX, 512>>>((const float*)p_q, (float*)p_qgr,
                                 (const float*)p_k, (float*)p_kgr);
    // 5. BOTH score GEMMs in one launch (tf32 mma, 2 CTAs/SM)
    bgemm_nt_mma<<<dim3(4, 4, 2 * BHX), 256>>>(
        (const float*)p_q, (const float*)p_k, (const float*)p_qgr, (const float*)p_kgr,
        (float*)p_qk, (float*)p_dd);
    // 6. fused channel-mix + softmax -> attn output region of d_out
    float* attn_out = out + OUT_ATTN_OFF;
    mix_softmax<<<MTOK, 512>>>(scale, riem, grass, conv_w, conv_b, attn_out);
    // 7. attn @ V (tf32 mma) -> [B,N,C] layout
    bgemm_av_mma<<<dim3(4, BHX), 256>>>(attn_out);
    // 8. output projection + residual with original src (tf32 mma)
    mmgemm_abt<EPI_RESID><<<dim3(CCX / 128, MTOK / 128), 256>>>(
        (const float*)p_attnv, proj_w, proj_b, src, (float*)p_src1, MTOK, CCX, CCX);
    // 9. norm1
    ln_kernel<<<MTOK, 128>>>((const float*)p_src1, n1_w, n1_b, (float*)p_x);
    // 10. FF lin1 + exact GELU (tf32 mma)
    mmgemm_abt<EPI_GELU><<<dim3(FFD / 128, MTOK / 128), 256>>>(
        (const float*)p_x, l1_w, l1_b, nullptr, (float*)p_hff, MTOK, FFD, CCX);
    // 11. FF lin2 + residual -> src part of d_out (tf32 mma)
    mmgemm_abt<EPI_RESID><<<dim3(CCX / 128, MTOK / 128), 256>>>(
        (const float*)p_hff, l2_w, l2_b, (const float*)p_x, out, MTOK, CCX, FFD);

    (void)in_sizes; (void)n_in; (void)out_size;
}